// round 10
// baseline (speedup 1.0000x reference)
#include <cuda_runtime.h>
#include <cuda_bf16.h>
#include <mma.h>
#include <math.h>

using namespace nvcuda;

// Problem constants (fixed shapes)
#define BSZ   4
#define SEQ   1024
#define DM    512
#define NH    8
#define DQ    64
#define M_TOT (BSZ*SEQ)     // 4096 tokens
#define NBH   (BSZ*NH)      // 32 (batch,head) pairs
#define BM    64            // token tile rows
#define NTILE (M_TOT/BM)    // 64 token tiles
#define TPB   16            // tiles per batch

// -------------------- device scratch --------------------
__device__ __nv_bfloat16 g_Abf[M_TOT * DM];   // 4 MB bf16 ctx
__device__ __nv_bfloat16 g_Bbf[2*DM * DM];    // 1 MB bf16 [Wq;Wk]
__device__ float g_Sf[NBH * SEQ];
__device__ float g_Sb[NBH * SEQ];
__device__ float g_G [NBH * SEQ];
__device__ float g_band[NBH * SEQ];
// halo: biased q/k vectors at tile edges, [head][tile][64]
__device__ float g_qF[NH * NTILE * DQ];
__device__ float g_qL[NH * NTILE * DQ];
__device__ float g_kF[NH * NTILE * DQ];
__device__ float g_kL[NH * NTILE * DQ];

// -------------------- Kernel 0: fp32 -> bf16 conversion prepass ----------------
__global__ __launch_bounds__(256) void cvt_kernel(
    const float* __restrict__ ctx,
    const float* __restrict__ Wq,
    const float* __restrict__ Wk)
{
    const int CTX_G = (M_TOT * DM) / 8;     // 262144
    const int W_G   = (DM * DM) / 8;        // 32768
    int idx = blockIdx.x * 256 + threadIdx.x;
    if (idx >= CTX_G + 2 * W_G) return;

    const float* src;
    __nv_bfloat16* dst;
    if (idx < CTX_G) {
        src = ctx + (size_t)idx * 8;
        dst = g_Abf + (size_t)idx * 8;
    } else if (idx < CTX_G + W_G) {
        int j = idx - CTX_G;
        src = Wq + (size_t)j * 8;
        dst = g_Bbf + (size_t)j * 8;
    } else {
        int j = idx - CTX_G - W_G;
        src = Wk + (size_t)j * 8;
        dst = g_Bbf + (size_t)(W_G * 8) + (size_t)j * 8;
    }
    float4 v0 = *(const float4*)(src);
    float4 v1 = *(const float4*)(src + 4);
    __nv_bfloat162 b0 = __floats2bfloat162_rn(v0.x, v0.y);
    __nv_bfloat162 b1 = __floats2bfloat162_rn(v0.z, v0.w);
    __nv_bfloat162 b2 = __floats2bfloat162_rn(v1.x, v1.y);
    __nv_bfloat162 b3 = __floats2bfloat162_rn(v1.z, v1.w);
    uint4 packed;
    packed.x = *(unsigned*)&b0; packed.y = *(unsigned*)&b1;
    packed.z = *(unsigned*)&b2; packed.w = *(unsigned*)&b3;
    *(uint4*)dst = packed;
}

// -------------------- Kernel 1: fused GEMM + banded-dot epilogue ---------------
// Block (h, m): C[64 tokens of tile m][ Qh feats 0..63 | Kh feats 64..127 ]
#define BN   128
#define BKK  32
#define KPAD 40
#define CLD  132
#define SMEM_AB_BYTES  ((BM + BN) * KPAD * 2)    // 15360
#define SMEM_CST_BYTES (BM * CLD * 4)            // 33792
#define SMEM_TOTAL_GEMM (SMEM_CST_BYTES + 512)

__global__ __launch_bounds__(128) void gemm_band_kernel(
    const float* __restrict__ bq, const float* __restrict__ bk)
{
    extern __shared__ char dsm[];
    __nv_bfloat16 (*As)[KPAD] = (__nv_bfloat16(*)[KPAD])dsm;                       // [BM]
    __nv_bfloat16 (*Bs)[KPAD] = (__nv_bfloat16(*)[KPAD])(dsm + BM*KPAD*2);         // [BN]
    float (*Cst)[CLD] = (float(*)[CLD])dsm;                 // reuses As/Bs after MMAs
    float* bqs = (float*)(dsm + SMEM_CST_BYTES);
    float* bks = bqs + DQ;

    const int h  = blockIdx.x;           // head 0..7
    const int m  = blockIdx.y;           // token tile 0..63
    const int tid  = threadIdx.x;        // 0..127
    const int warp = tid >> 5;           // 0..3
    const int lane = tid & 31;
    const int wm = warp & 1;             // 2 warps along M (32 rows each)
    const int wn = warp >> 1;            // 2 warps along N (64 cols each)

    // head-sliced biases into smem
    if (tid < DQ)        bqs[tid] = bq[h*DQ + tid];
    else                 bks[tid - DQ] = bk[h*DQ + (tid - DQ)];

    wmma::fragment<wmma::accumulator,16,16,16,float> acc[2][4];
    #pragma unroll
    for (int mm = 0; mm < 2; mm++)
        #pragma unroll
        for (int nn = 0; nn < 4; nn++)
            wmma::fill_fragment(acc[mm][nn], 0.0f);

    // load mapping: A tile 64x32 bf16 = 256 uint4-groups (2/thr);
    //               B tile 128x32     = 512 groups (4/thr)
    const int rA0 = tid >> 1,          cA0 = (tid & 1) * 16;          // 2 groups/row? no:
    // A: 64 rows x 4 groups(8 bf16 each) = 256; idx = tid + 128*j, j<2
    // B: 128 rows x 4 groups = 512;        idx = tid + 128*j, j<4
    int rAj[2], cAj[2];
    #pragma unroll
    for (int j = 0; j < 2; j++) { int idx = tid + 128*j; rAj[j] = idx >> 2; cAj[j] = (idx & 3) * 8; }
    int rBj[4], cBj[4];
    const __nv_bfloat16* srcB[4];
    #pragma unroll
    for (int j = 0; j < 4; j++) {
        int idx = tid + 128*j; rBj[j] = idx >> 2; cBj[j] = (idx & 3) * 8;
        int r = rBj[j];
        int wrow = (r < DQ) ? (h*DQ + r) : (DM + h*DQ + (r - DQ));
        srcB[j] = &g_Bbf[(size_t)wrow * DM];
    }
    const __nv_bfloat16* srcA = &g_Abf[(size_t)(m*BM) * DM];
    (void)rA0; (void)cA0;

    // preload K-slab 0 into regs
    uint4 av[2], bv[4];
    #pragma unroll
    for (int j = 0; j < 2; j++) av[j] = *(const uint4*)(srcA + (size_t)rAj[j]*DM + cAj[j]);
    #pragma unroll
    for (int j = 0; j < 4; j++) bv[j] = *(const uint4*)(srcB[j] + cBj[j]);

    const int NIT = DM / BKK;  // 16
    for (int kt = 0; kt < NIT; kt++) {
        __syncthreads();                       // prior-iter smem consumers done
        #pragma unroll
        for (int j = 0; j < 2; j++) *(uint4*)&As[rAj[j]][cAj[j]] = av[j];
        #pragma unroll
        for (int j = 0; j < 4; j++) *(uint4*)&Bs[rBj[j]][cBj[j]] = bv[j];
        __syncthreads();

        if (kt + 1 < NIT) {
            const int kg = (kt + 1) * BKK;
            #pragma unroll
            for (int j = 0; j < 2; j++) av[j] = *(const uint4*)(srcA + (size_t)rAj[j]*DM + kg + cAj[j]);
            #pragma unroll
            for (int j = 0; j < 4; j++) bv[j] = *(const uint4*)(srcB[j] + kg + cBj[j]);
        }

        #pragma unroll
        for (int kk = 0; kk < BKK; kk += 16) {
            wmma::fragment<wmma::matrix_a,16,16,16,__nv_bfloat16,wmma::row_major> af[2];
            wmma::fragment<wmma::matrix_b,16,16,16,__nv_bfloat16,wmma::col_major> bf[4];
            #pragma unroll
            for (int mm = 0; mm < 2; mm++)
                wmma::load_matrix_sync(af[mm], &As[wm*32 + mm*16][kk], KPAD);
            #pragma unroll
            for (int nn = 0; nn < 4; nn++)
                wmma::load_matrix_sync(bf[nn], &Bs[wn*64 + nn*16][kk], KPAD);
            #pragma unroll
            for (int mm = 0; mm < 2; mm++)
                #pragma unroll
                for (int nn = 0; nn < 4; nn++)
                    wmma::mma_sync(acc[mm][nn], af[mm], bf[nn], acc[mm][nn]);
        }
    }
    __syncthreads();   // all warps done reading As/Bs before Cst overwrite

    // ---- stage C into smem ----
    #pragma unroll
    for (int mm = 0; mm < 2; mm++)
        #pragma unroll
        for (int nn = 0; nn < 4; nn++)
            wmma::store_matrix_sync(&Cst[wm*32 + mm*16][wn*64 + nn*16],
                                    acc[mm][nn], CLD, wmma::mem_row_major);
    __syncthreads();

    // ---- halo: biased q/k vectors at tile edges (rows 0 and 63) ----
    {
        int hm = (h*NTILE + m)*DQ;
        if (tid < DQ) {
            int d = tid;
            g_qF[hm + d] = Cst[0][d]      + bqs[d];
            g_kF[hm + d] = Cst[0][DQ + d] + bks[d];
        } else {
            int d = tid - DQ;
            g_qL[hm + d] = Cst[BM-1][d]      + bqs[d];
            g_kL[hm + d] = Cst[BM-1][DQ + d] + bks[d];
        }
    }

    // ---- interior banded dots: warp w -> rows w*16 .. w*16+15 ----
    const int d = lane * 2;
    float2 bqv = *(float2*)&bqs[d];
    float2 bkv = *(float2*)&bks[d];
    #pragma unroll
    for (int rr = 0; rr < 16; rr++) {
        int r = warp*16 + rr;
        float2 qv = *(float2*)&Cst[r][d];
        float q0 = qv.x + bqv.x, q1 = qv.y + bqv.y;
        float sf = 0.f, sb = 0.f;
        if (r < BM-1) {
            float2 kv = *(float2*)&Cst[r+1][DQ + d];
            sf = q0*(kv.x + bkv.x) + q1*(kv.y + bkv.y);
        }
        if (r > 0) {
            float2 kv = *(float2*)&Cst[r-1][DQ + d];
            sb = q0*(kv.x + bkv.x) + q1*(kv.y + bkv.y);
        }
        #pragma unroll
        for (int off = 16; off; off >>= 1) {
            sf += __shfl_down_sync(0xffffffffu, sf, off);
            sb += __shfl_down_sync(0xffffffffu, sb, off);
        }
        if (lane == 0) {
            int row = m*BM + r;
            int b = row >> 10;
            int i = row & (SEQ - 1);
            int idx = (b*NH + h)*SEQ + i;
            if (r < BM-1) g_Sf[idx] = sf * (1.0f / DM);
            if (r > 0)    g_Sb[idx] = sb * (1.0f / DM);
        }
    }
}

// -------------------- Kernel 2: boundary dots + softmax + prefix scan ----------
__global__ __launch_bounds__(1024) void scan_kernel(const int* __restrict__ amask)
{
    int bh = blockIdx.x;                 // 0..31
    int b  = bh >> 3;
    int h  = bh & 7;
    int t  = threadIdx.x;                // 0..1023
    int lane = t & 31, wid = t >> 5;

    __shared__ float b_sh[SEQ];
    __shared__ float wsum[32];
    __shared__ float sf_fix[TPB], sb_fix[TPB];

    // tile-boundary dots: warps 0..14 fwd (j=wid), warps 16..30 bwd (j=wid-15)
    if (wid < TPB-1) {
        int mm = b*TPB + wid;            // fwd at token t=64*wid+63
        float acc = 0.f;
        #pragma unroll
        for (int d = lane; d < DQ; d += 32)
            acc += g_qL[(h*NTILE + mm)*DQ + d] * g_kF[(h*NTILE + mm + 1)*DQ + d];
        #pragma unroll
        for (int off = 16; off; off >>= 1) acc += __shfl_down_sync(0xffffffffu, acc, off);
        if (lane == 0) sf_fix[wid] = acc * (1.0f / DM);
    } else if (wid >= 16 && wid < 16 + TPB-1) {
        int j = wid - 15;                // bwd at token t=64*j, j=1..15
        int mm = b*TPB + j;
        float acc = 0.f;
        #pragma unroll
        for (int d = lane; d < DQ; d += 32)
            acc += g_qF[(h*NTILE + mm)*DQ + d] * g_kL[(h*NTILE + mm - 1)*DQ + d];
        #pragma unroll
        for (int off = 16; off; off >>= 1) acc += __shfl_down_sync(0xffffffffu, acc, off);
        if (lane == 0) sb_fix[j] = acc * (1.0f / DM);
    }
    __syncthreads();

    float sf = g_Sf[bh*SEQ + t];
    float sb = g_Sb[bh*SEQ + t];
    if ((t & 63) == 63 && t < SEQ-1) sf = sf_fix[t >> 6];
    if ((t & 63) == 0  && t > 0)     sb = sb_fix[t >> 6];

    bool vf = (t < SEQ-1) && (amask[b*SEQ + t + 1] != 0);
    bool vb = (t > 0)     && (amask[b*SEQ + t - 1] != 0);

    float a, bb;
    if (vf | vb) {
        float mx = fmaxf(vf ? sf : -3.4e38f, vb ? sb : -3.4e38f);
        float ea = vf ? __expf(sf - mx) : 0.f;
        float eb = vb ? __expf(sb - mx) : 0.f;
        float den = ea + eb;
        a  = ea / den;
        bb = eb / den;
    } else {
        a = bb = 1.0f / SEQ;
    }
    b_sh[t] = bb;
    __syncthreads();

    float g = 0.f;
    if (t < SEQ-1) {
        float ph = sqrtf(a * b_sh[t+1] + 1e-9f);
        g_band[bh*SEQ + t] = ph;
        g = logf(ph + 1e-9f);
    }

    float incl = g;
    #pragma unroll
    for (int off = 1; off < 32; off <<= 1) {
        float n = __shfl_up_sync(0xffffffffu, incl, off);
        if (lane >= off) incl += n;
    }
    if (lane == 31) wsum[wid] = incl;
    __syncthreads();
    if (wid == 0) {
        float w = wsum[lane];
        #pragma unroll
        for (int off = 1; off < 32; off <<= 1) {
            float n = __shfl_up_sync(0xffffffffu, w, off);
            if (lane >= off) w += n;
        }
        wsum[lane] = w;
    }
    __syncthreads();
    float base = (wid > 0) ? wsum[wid-1] : 0.f;
    g_G[bh*SEQ + t] = base + incl - g;   // exclusive prefix
}

// -------------------- Kernel 3: materialize outputs (8 rows per block) ---------
__global__ __launch_bounds__(256) void out_kernel(float* __restrict__ out, int write_ph)
{
    const float SQRT_EPS = 3.1622776601683795e-5f;
    const float EPS = 1e-9f;

    int blk = blockIdx.x;                // bh*128 + rowTile
    int bh  = blk >> 7;
    int r0  = (blk & 127) << 3;          // first row i of 8
    int k0  = threadIdx.x << 2;

    const float* Gp = g_G + bh*SEQ;

    __shared__ float Gi_s[8];
    __shared__ float band_s[9];          // band[r0-1 .. r0+7]
    if (threadIdx.x < 8) Gi_s[threadIdx.x] = Gp[r0 + threadIdx.x];
    if (threadIdx.x < 9) {
        int ib = r0 - 1 + threadIdx.x;
        band_s[threadIdx.x] = (ib >= 0 && ib < SEQ-1) ? g_band[bh*SEQ + ib] : 0.f;
    }
    __syncthreads();

    float4 gk = *(const float4*)&Gp[k0];
    size_t base = (size_t)(bh*SEQ + r0) * SEQ + k0;
    size_t pbase = (size_t)NBH*SEQ*SEQ + base;

    #pragma unroll
    for (int r = 0; r < 8; r++) {
        int i = r0 + r;
        float Gi = Gi_s[r];
        float4 o;
        int k;
        k = k0 + 0; o.x = (k == i) ? SQRT_EPS : (__expf((k > i) ? gk.x - Gi : Gi - gk.x) + EPS);
        k = k0 + 1; o.y = (k == i) ? SQRT_EPS : (__expf((k > i) ? gk.y - Gi : Gi - gk.y) + EPS);
        k = k0 + 2; o.z = (k == i) ? SQRT_EPS : (__expf((k > i) ? gk.z - Gi : Gi - gk.z) + EPS);
        k = k0 + 3; o.w = (k == i) ? SQRT_EPS : (__expf((k > i) ? gk.w - Gi : Gi - gk.w) + EPS);
        __stcs((float4*)(out + base + (size_t)r*SEQ), o);

        if (write_ph) {
            float4 p = make_float4(SQRT_EPS, SQRT_EPS, SQRT_EPS, SQRT_EPS);
            int d = (i - 1) - k0;
            if (d >= 0 && d < 4) {
                float v = band_s[r];
                if (d == 0) p.x = v; else if (d == 1) p.y = v; else if (d == 2) p.z = v; else p.w = v;
            }
            d = (i + 1) - k0;
            if (d >= 0 && d < 4) {
                float v = band_s[r + 1];
                if (d == 0) p.x = v; else if (d == 1) p.y = v; else if (d == 2) p.z = v; else p.w = v;
            }
            __stcs((float4*)(out + pbase + (size_t)r*SEQ), p);
        }
    }
}

// -------------------- launch ---------------------------------------------------
extern "C" void kernel_launch(void* const* d_in, const int* in_sizes, int n_in,
                              void* d_out, int out_size)
{
    const float* ctx   = (const float*)d_in[0];   // (4,1024,512) fp32
    const int*   amask = (const int*)  d_in[1];   // (4,1024) int32
    const float* Wq    = (const float*)d_in[2];   // (512,512)
    const float* bq    = (const float*)d_in[3];   // (512,)
    const float* Wk    = (const float*)d_in[4];   // (512,512)
    const float* bk    = (const float*)d_in[5];   // (512,)
    float* out = (float*)d_out;

    long long total = (long long)NBH * SEQ * SEQ;
    int write_ph = ((long long)out_size >= 2 * total) ? 1 : 0;

    cudaFuncSetAttribute(gemm_band_kernel,
                         cudaFuncAttributeMaxDynamicSharedMemorySize, SMEM_TOTAL_GEMM);

    const int CVT_G = (M_TOT*DM + 2*DM*DM) / 8;   // 327680 groups
    cvt_kernel<<<(CVT_G + 255) / 256, 256>>>(ctx, Wq, Wk);

    dim3 ggrid(NH, NTILE);               // (8, 64)
    gemm_band_kernel<<<ggrid, 128, SMEM_TOTAL_GEMM>>>(bq, bk);
    scan_kernel<<<NBH, 1024>>>(amask);
    out_kernel<<<NBH * SEQ / 8, 256>>>(out, write_ph);
}

// round 11
// speedup vs baseline: 1.0106x; 1.0106x over previous
#include <cuda_runtime.h>
#include <cuda_bf16.h>
#include <mma.h>
#include <math.h>

using namespace nvcuda;

// Problem constants (fixed shapes)
#define BSZ   4
#define SEQ   1024
#define DM    512
#define NH    8
#define DQ    64
#define M_TOT (BSZ*SEQ)     // 4096 tokens
#define NBH   (BSZ*NH)      // 32 (batch,head) pairs
#define BM    64            // token tile rows
#define NTILE (M_TOT/BM)    // 64 token tiles
#define TPB   16            // tiles per batch

// -------------------- device scratch --------------------
__device__ __nv_bfloat16 g_Abf[M_TOT * DM];   // 4 MB bf16 ctx
__device__ __nv_bfloat16 g_Bbf[2*DM * DM];    // 1 MB bf16 [Wq;Wk]
__device__ float g_Sf[NBH * SEQ];
__device__ float g_Sb[NBH * SEQ];
__device__ float g_G [NBH * SEQ];
__device__ float g_band[NBH * SEQ];
// halo: biased q/k vectors at tile edges, [head][tile][64]
__device__ float g_qF[NH * NTILE * DQ];
__device__ float g_qL[NH * NTILE * DQ];
__device__ float g_kF[NH * NTILE * DQ];
__device__ float g_kL[NH * NTILE * DQ];

// -------------------- Kernel 0: fp32 -> bf16 conversion prepass ----------------
__global__ __launch_bounds__(256) void cvt_kernel(
    const float* __restrict__ ctx,
    const float* __restrict__ Wq,
    const float* __restrict__ Wk)
{
    const int CTX_G = (M_TOT * DM) / 8;     // 262144
    const int W_G   = (DM * DM) / 8;        // 32768
    int idx = blockIdx.x * 256 + threadIdx.x;
    if (idx >= CTX_G + 2 * W_G) return;

    const float* src;
    __nv_bfloat16* dst;
    if (idx < CTX_G) {
        src = ctx + (size_t)idx * 8;
        dst = g_Abf + (size_t)idx * 8;
    } else if (idx < CTX_G + W_G) {
        int j = idx - CTX_G;
        src = Wq + (size_t)j * 8;
        dst = g_Bbf + (size_t)j * 8;
    } else {
        int j = idx - CTX_G - W_G;
        src = Wk + (size_t)j * 8;
        dst = g_Bbf + (size_t)(W_G * 8) + (size_t)j * 8;
    }
    float4 v0 = *(const float4*)(src);
    float4 v1 = *(const float4*)(src + 4);
    __nv_bfloat162 b0 = __floats2bfloat162_rn(v0.x, v0.y);
    __nv_bfloat162 b1 = __floats2bfloat162_rn(v0.z, v0.w);
    __nv_bfloat162 b2 = __floats2bfloat162_rn(v1.x, v1.y);
    __nv_bfloat162 b3 = __floats2bfloat162_rn(v1.z, v1.w);
    uint4 packed;
    packed.x = *(unsigned*)&b0; packed.y = *(unsigned*)&b1;
    packed.z = *(unsigned*)&b2; packed.w = *(unsigned*)&b3;
    *(uint4*)dst = packed;
}

// -------------------- Kernel 1: fused GEMM + banded-dot epilogue ---------------
// Block (h, m): C[64 tokens of tile m][ Qh feats 0..63 | Kh feats 64..127 ]
#define BN   128
#define BKK  32
#define KPAD 40
#define CLD  132
#define SMEM_AB_BYTES  ((BM + BN) * KPAD * 2)    // 15360
#define SMEM_CST_BYTES (BM * CLD * 4)            // 33792
#define SMEM_TOTAL_GEMM (SMEM_CST_BYTES + 512)

__global__ __launch_bounds__(128) void gemm_band_kernel(
    const float* __restrict__ bq, const float* __restrict__ bk)
{
    extern __shared__ char dsm[];
    __nv_bfloat16 (*As)[KPAD] = (__nv_bfloat16(*)[KPAD])dsm;                       // [BM]
    __nv_bfloat16 (*Bs)[KPAD] = (__nv_bfloat16(*)[KPAD])(dsm + BM*KPAD*2);         // [BN]
    float (*Cst)[CLD] = (float(*)[CLD])dsm;                 // reuses As/Bs after MMAs
    float* bqs = (float*)(dsm + SMEM_CST_BYTES);
    float* bks = bqs + DQ;

    const int h  = blockIdx.x;           // head 0..7
    const int m  = blockIdx.y;           // token tile 0..63
    const int tid  = threadIdx.x;        // 0..127
    const int warp = tid >> 5;           // 0..3
    const int lane = tid & 31;
    const int wm = warp & 1;             // 2 warps along M (32 rows each)
    const int wn = warp >> 1;            // 2 warps along N (64 cols each)

    // head-sliced biases into smem
    if (tid < DQ)        bqs[tid] = bq[h*DQ + tid];
    else                 bks[tid - DQ] = bk[h*DQ + (tid - DQ)];

    wmma::fragment<wmma::accumulator,16,16,16,float> acc[2][4];
    #pragma unroll
    for (int mm = 0; mm < 2; mm++)
        #pragma unroll
        for (int nn = 0; nn < 4; nn++)
            wmma::fill_fragment(acc[mm][nn], 0.0f);

    // load mapping: A tile 64x32 bf16 = 256 uint4-groups (2/thr);
    //               B tile 128x32     = 512 groups (4/thr)
    const int rA0 = tid >> 1,          cA0 = (tid & 1) * 16;          // 2 groups/row? no:
    // A: 64 rows x 4 groups(8 bf16 each) = 256; idx = tid + 128*j, j<2
    // B: 128 rows x 4 groups = 512;        idx = tid + 128*j, j<4
    int rAj[2], cAj[2];
    #pragma unroll
    for (int j = 0; j < 2; j++) { int idx = tid + 128*j; rAj[j] = idx >> 2; cAj[j] = (idx & 3) * 8; }
    int rBj[4], cBj[4];
    const __nv_bfloat16* srcB[4];
    #pragma unroll
    for (int j = 0; j < 4; j++) {
        int idx = tid + 128*j; rBj[j] = idx >> 2; cBj[j] = (idx & 3) * 8;
        int r = rBj[j];
        int wrow = (r < DQ) ? (h*DQ + r) : (DM + h*DQ + (r - DQ));
        srcB[j] = &g_Bbf[(size_t)wrow * DM];
    }
    const __nv_bfloat16* srcA = &g_Abf[(size_t)(m*BM) * DM];
    (void)rA0; (void)cA0;

    // preload K-slab 0 into regs
    uint4 av[2], bv[4];
    #pragma unroll
    for (int j = 0; j < 2; j++) av[j] = *(const uint4*)(srcA + (size_t)rAj[j]*DM + cAj[j]);
    #pragma unroll
    for (int j = 0; j < 4; j++) bv[j] = *(const uint4*)(srcB[j] + cBj[j]);

    const int NIT = DM / BKK;  // 16
    for (int kt = 0; kt < NIT; kt++) {
        __syncthreads();                       // prior-iter smem consumers done
        #pragma unroll
        for (int j = 0; j < 2; j++) *(uint4*)&As[rAj[j]][cAj[j]] = av[j];
        #pragma unroll
        for (int j = 0; j < 4; j++) *(uint4*)&Bs[rBj[j]][cBj[j]] = bv[j];
        __syncthreads();

        if (kt + 1 < NIT) {
            const int kg = (kt + 1) * BKK;
            #pragma unroll
            for (int j = 0; j < 2; j++) av[j] = *(const uint4*)(srcA + (size_t)rAj[j]*DM + kg + cAj[j]);
            #pragma unroll
            for (int j = 0; j < 4; j++) bv[j] = *(const uint4*)(srcB[j] + kg + cBj[j]);
        }

        #pragma unroll
        for (int kk = 0; kk < BKK; kk += 16) {
            wmma::fragment<wmma::matrix_a,16,16,16,__nv_bfloat16,wmma::row_major> af[2];
            wmma::fragment<wmma::matrix_b,16,16,16,__nv_bfloat16,wmma::col_major> bf[4];
            #pragma unroll
            for (int mm = 0; mm < 2; mm++)
                wmma::load_matrix_sync(af[mm], &As[wm*32 + mm*16][kk], KPAD);
            #pragma unroll
            for (int nn = 0; nn < 4; nn++)
                wmma::load_matrix_sync(bf[nn], &Bs[wn*64 + nn*16][kk], KPAD);
            #pragma unroll
            for (int mm = 0; mm < 2; mm++)
                #pragma unroll
                for (int nn = 0; nn < 4; nn++)
                    wmma::mma_sync(acc[mm][nn], af[mm], bf[nn], acc[mm][nn]);
        }
    }
    __syncthreads();   // all warps done reading As/Bs before Cst overwrite

    // ---- stage C into smem ----
    #pragma unroll
    for (int mm = 0; mm < 2; mm++)
        #pragma unroll
        for (int nn = 0; nn < 4; nn++)
            wmma::store_matrix_sync(&Cst[wm*32 + mm*16][wn*64 + nn*16],
                                    acc[mm][nn], CLD, wmma::mem_row_major);
    __syncthreads();

    // ---- halo: biased q/k vectors at tile edges (rows 0 and 63) ----
    {
        int hm = (h*NTILE + m)*DQ;
        if (tid < DQ) {
            int d = tid;
            g_qF[hm + d] = Cst[0][d]      + bqs[d];
            g_kF[hm + d] = Cst[0][DQ + d] + bks[d];
        } else {
            int d = tid - DQ;
            g_qL[hm + d] = Cst[BM-1][d]      + bqs[d];
            g_kL[hm + d] = Cst[BM-1][DQ + d] + bks[d];
        }
    }

    // ---- interior banded dots: warp w -> rows w*16 .. w*16+15 ----
    const int d = lane * 2;
    float2 bqv = *(float2*)&bqs[d];
    float2 bkv = *(float2*)&bks[d];
    #pragma unroll
    for (int rr = 0; rr < 16; rr++) {
        int r = warp*16 + rr;
        float2 qv = *(float2*)&Cst[r][d];
        float q0 = qv.x + bqv.x, q1 = qv.y + bqv.y;
        float sf = 0.f, sb = 0.f;
        if (r < BM-1) {
            float2 kv = *(float2*)&Cst[r+1][DQ + d];
            sf = q0*(kv.x + bkv.x) + q1*(kv.y + bkv.y);
        }
        if (r > 0) {
            float2 kv = *(float2*)&Cst[r-1][DQ + d];
            sb = q0*(kv.x + bkv.x) + q1*(kv.y + bkv.y);
        }
        #pragma unroll
        for (int off = 16; off; off >>= 1) {
            sf += __shfl_down_sync(0xffffffffu, sf, off);
            sb += __shfl_down_sync(0xffffffffu, sb, off);
        }
        if (lane == 0) {
            int row = m*BM + r;
            int b = row >> 10;
            int i = row & (SEQ - 1);
            int idx = (b*NH + h)*SEQ + i;
            if (r < BM-1) g_Sf[idx] = sf * (1.0f / DM);
            if (r > 0)    g_Sb[idx] = sb * (1.0f / DM);
        }
    }
}

// -------------------- Kernel 2: boundary dots + softmax + prefix scan ----------
__global__ __launch_bounds__(1024) void scan_kernel(const int* __restrict__ amask)
{
    int bh = blockIdx.x;                 // 0..31
    int b  = bh >> 3;
    int h  = bh & 7;
    int t  = threadIdx.x;                // 0..1023
    int lane = t & 31, wid = t >> 5;

    __shared__ float b_sh[SEQ];
    __shared__ float wsum[32];
    __shared__ float sf_fix[TPB], sb_fix[TPB];

    // tile-boundary dots: warps 0..14 fwd (j=wid), warps 16..30 bwd (j=wid-15)
    if (wid < TPB-1) {
        int mm = b*TPB + wid;            // fwd at token t=64*wid+63
        float acc = 0.f;
        #pragma unroll
        for (int d = lane; d < DQ; d += 32)
            acc += g_qL[(h*NTILE + mm)*DQ + d] * g_kF[(h*NTILE + mm + 1)*DQ + d];
        #pragma unroll
        for (int off = 16; off; off >>= 1) acc += __shfl_down_sync(0xffffffffu, acc, off);
        if (lane == 0) sf_fix[wid] = acc * (1.0f / DM);
    } else if (wid >= 16 && wid < 16 + TPB-1) {
        int j = wid - 15;                // bwd at token t=64*j, j=1..15
        int mm = b*TPB + j;
        float acc = 0.f;
        #pragma unroll
        for (int d = lane; d < DQ; d += 32)
            acc += g_qF[(h*NTILE + mm)*DQ + d] * g_kL[(h*NTILE + mm - 1)*DQ + d];
        #pragma unroll
        for (int off = 16; off; off >>= 1) acc += __shfl_down_sync(0xffffffffu, acc, off);
        if (lane == 0) sb_fix[j] = acc * (1.0f / DM);
    }
    __syncthreads();

    float sf = g_Sf[bh*SEQ + t];
    float sb = g_Sb[bh*SEQ + t];
    if ((t & 63) == 63 && t < SEQ-1) sf = sf_fix[t >> 6];
    if ((t & 63) == 0  && t > 0)     sb = sb_fix[t >> 6];

    bool vf = (t < SEQ-1) && (amask[b*SEQ + t + 1] != 0);
    bool vb = (t > 0)     && (amask[b*SEQ + t - 1] != 0);

    float a, bb;
    if (vf | vb) {
        float mx = fmaxf(vf ? sf : -3.4e38f, vb ? sb : -3.4e38f);
        float ea = vf ? __expf(sf - mx) : 0.f;
        float eb = vb ? __expf(sb - mx) : 0.f;
        float den = ea + eb;
        a  = ea / den;
        bb = eb / den;
    } else {
        a = bb = 1.0f / SEQ;
    }
    b_sh[t] = bb;
    __syncthreads();

    float g = 0.f;
    if (t < SEQ-1) {
        float ph = sqrtf(a * b_sh[t+1] + 1e-9f);
        g_band[bh*SEQ + t] = ph;
        g = logf(ph + 1e-9f);
    }

    float incl = g;
    #pragma unroll
    for (int off = 1; off < 32; off <<= 1) {
        float n = __shfl_up_sync(0xffffffffu, incl, off);
        if (lane >= off) incl += n;
    }
    if (lane == 31) wsum[wid] = incl;
    __syncthreads();
    if (wid == 0) {
        float w = wsum[lane];
        #pragma unroll
        for (int off = 1; off < 32; off <<= 1) {
            float n = __shfl_up_sync(0xffffffffu, w, off);
            if (lane >= off) w += n;
        }
        wsum[lane] = w;
    }
    __syncthreads();
    float base = (wid > 0) ? wsum[wid-1] : 0.f;
    g_G[bh*SEQ + t] = base + incl - g;   // exclusive prefix
}

// -------------------- Kernel 3: materialize outputs (8 rows per block) ---------
__global__ __launch_bounds__(256) void out_kernel(float* __restrict__ out, int write_ph)
{
    const float SQRT_EPS = 3.1622776601683795e-5f;
    const float EPS = 1e-9f;

    int blk = blockIdx.x;                // bh*128 + rowTile
    int bh  = blk >> 7;
    int r0  = (blk & 127) << 3;          // first row i of 8
    int k0  = threadIdx.x << 2;

    const float* Gp = g_G + bh*SEQ;

    __shared__ float Gi_s[8];
    __shared__ float band_s[9];          // band[r0-1 .. r0+7]
    if (threadIdx.x < 8) Gi_s[threadIdx.x] = Gp[r0 + threadIdx.x];
    if (threadIdx.x < 9) {
        int ib = r0 - 1 + threadIdx.x;
        band_s[threadIdx.x] = (ib >= 0 && ib < SEQ-1) ? g_band[bh*SEQ + ib] : 0.f;
    }
    __syncthreads();

    float4 gk = *(const float4*)&Gp[k0];
    size_t base = (size_t)(bh*SEQ + r0) * SEQ + k0;
    size_t pbase = (size_t)NBH*SEQ*SEQ + base;

    #pragma unroll
    for (int r = 0; r < 8; r++) {
        int i = r0 + r;
        float Gi = Gi_s[r];
        float4 o;
        int k;
        k = k0 + 0; o.x = (k == i) ? SQRT_EPS : (__expf((k > i) ? gk.x - Gi : Gi - gk.x) + EPS);
        k = k0 + 1; o.y = (k == i) ? SQRT_EPS : (__expf((k > i) ? gk.y - Gi : Gi - gk.y) + EPS);
        k = k0 + 2; o.z = (k == i) ? SQRT_EPS : (__expf((k > i) ? gk.z - Gi : Gi - gk.z) + EPS);
        k = k0 + 3; o.w = (k == i) ? SQRT_EPS : (__expf((k > i) ? gk.w - Gi : Gi - gk.w) + EPS);
        __stcs((float4*)(out + base + (size_t)r*SEQ), o);

        if (write_ph) {
            float4 p = make_float4(SQRT_EPS, SQRT_EPS, SQRT_EPS, SQRT_EPS);
            int d = (i - 1) - k0;
            if (d >= 0 && d < 4) {
                float v = band_s[r];
                if (d == 0) p.x = v; else if (d == 1) p.y = v; else if (d == 2) p.z = v; else p.w = v;
            }
            d = (i + 1) - k0;
            if (d >= 0 && d < 4) {
                float v = band_s[r + 1];
                if (d == 0) p.x = v; else if (d == 1) p.y = v; else if (d == 2) p.z = v; else p.w = v;
            }
            __stcs((float4*)(out + pbase + (size_t)r*SEQ), p);
        }
    }
}

// -------------------- launch ---------------------------------------------------
extern "C" void kernel_launch(void* const* d_in, const int* in_sizes, int n_in,
                              void* d_out, int out_size)
{
    const float* ctx   = (const float*)d_in[0];   // (4,1024,512) fp32
    const int*   amask = (const int*)  d_in[1];   // (4,1024) int32
    const float* Wq    = (const float*)d_in[2];   // (512,512)
    const float* bq    = (const float*)d_in[3];   // (512,)
    const float* Wk    = (const float*)d_in[4];   // (512,512)
    const float* bk    = (const float*)d_in[5];   // (512,)
    float* out = (float*)d_out;

    long long total = (long long)NBH * SEQ * SEQ;
    int write_ph = ((long long)out_size >= 2 * total) ? 1 : 0;

    cudaFuncSetAttribute(gemm_band_kernel,
                         cudaFuncAttributeMaxDynamicSharedMemorySize, SMEM_TOTAL_GEMM);

    const int CVT_G = (M_TOT*DM + 2*DM*DM) / 8;   // 327680 groups
    cvt_kernel<<<(CVT_G + 255) / 256, 256>>>(ctx, Wq, Wk);

    dim3 ggrid(NH, NTILE);               // (8, 64)
    gemm_band_kernel<<<ggrid, 128, SMEM_TOTAL_GEMM>>>(bq, bk);
    scan_kernel<<<NBH, 1024>>>(amask);
    out_kernel<<<NBH * SEQ / 8, 256>>>(out, write_ph);
}

// round 12
// speedup vs baseline: 1.0899x; 1.0785x over previous
#include <cuda_runtime.h>
#include <cuda_bf16.h>
#include <mma.h>
#include <math.h>

using namespace nvcuda;

// Problem constants (fixed shapes)
#define BSZ   4
#define SEQ   1024
#define DM    512
#define NH    8
#define DQ    64
#define M_TOT (BSZ*SEQ)     // 4096 tokens
#define NBH   (BSZ*NH)      // 32 (batch,head) pairs
#define BM    64            // token tile rows
#define NTILE (M_TOT/BM)    // 64 token tiles
#define TPB   16            // tiles per batch

// -------------------- device scratch --------------------
__device__ __nv_bfloat16 g_Abf[M_TOT * DM];   // 4 MB bf16 ctx
__device__ __nv_bfloat16 g_Bbf[2*DM * DM];    // 1 MB bf16 [Wq;Wk]
__device__ float g_Sf[NBH * SEQ];
__device__ float g_Sb[NBH * SEQ];
__device__ float g_G [NBH * SEQ];
__device__ float g_band[NBH * SEQ];
// halo: biased q/k vectors at tile edges, [head][tile][64]
__device__ float g_qF[NH * NTILE * DQ];
__device__ float g_qL[NH * NTILE * DQ];
__device__ float g_kF[NH * NTILE * DQ];
__device__ float g_kL[NH * NTILE * DQ];

// -------------------- cp.async helpers --------------------
#define CP_ASYNC16(dst_u32, src_ptr) \
    asm volatile("cp.async.cg.shared.global [%0], [%1], 16;\n" :: "r"(dst_u32), "l"(src_ptr))
#define CP_COMMIT() asm volatile("cp.async.commit_group;\n" ::: "memory")
#define CP_WAIT2()  asm volatile("cp.async.wait_group 2;\n" ::: "memory")
#define CP_WAIT0()  asm volatile("cp.async.wait_group 0;\n" ::: "memory")

// -------------------- Kernel 0: fp32 -> bf16 conversion prepass ----------------
__global__ __launch_bounds__(256) void cvt_kernel(
    const float* __restrict__ ctx,
    const float* __restrict__ Wq,
    const float* __restrict__ Wk)
{
    const int CTX_G = (M_TOT * DM) / 8;     // 262144
    const int W_G   = (DM * DM) / 8;        // 32768
    int idx = blockIdx.x * 256 + threadIdx.x;
    if (idx >= CTX_G + 2 * W_G) return;

    const float* src;
    __nv_bfloat16* dst;
    if (idx < CTX_G) {
        src = ctx + (size_t)idx * 8;
        dst = g_Abf + (size_t)idx * 8;
    } else if (idx < CTX_G + W_G) {
        int j = idx - CTX_G;
        src = Wq + (size_t)j * 8;
        dst = g_Bbf + (size_t)j * 8;
    } else {
        int j = idx - CTX_G - W_G;
        src = Wk + (size_t)j * 8;
        dst = g_Bbf + (size_t)(W_G * 8) + (size_t)j * 8;
    }
    float4 v0 = *(const float4*)(src);
    float4 v1 = *(const float4*)(src + 4);
    __nv_bfloat162 b0 = __floats2bfloat162_rn(v0.x, v0.y);
    __nv_bfloat162 b1 = __floats2bfloat162_rn(v0.z, v0.w);
    __nv_bfloat162 b2 = __floats2bfloat162_rn(v1.x, v1.y);
    __nv_bfloat162 b3 = __floats2bfloat162_rn(v1.z, v1.w);
    uint4 packed;
    packed.x = *(unsigned*)&b0; packed.y = *(unsigned*)&b1;
    packed.z = *(unsigned*)&b2; packed.w = *(unsigned*)&b3;
    *(uint4*)dst = packed;
}

// -------------------- Kernel 1: fused GEMM + banded-dot epilogue ---------------
// Block (h, m): C[64 tokens of tile m][ Qh feats 0..63 | Kh feats 64..127 ]
#define BN   128
#define BKK  32
#define KPAD 40
#define NSTAGE 4
#define STAGE_BYTES ((BM + BN) * KPAD * 2)       // 15360 per stage
#define AS_OFF      0
#define BS_OFF      (BM * KPAD * 2)              // 5120 within stage
#define CLD  132
#define SMEM_CST_BYTES (BM * CLD * 4)            // 33792
#define SMEM_BIAS_OFF  (NSTAGE * STAGE_BYTES)    // 61440
#define SMEM_TOTAL_GEMM (SMEM_BIAS_OFF + 512)    // 61952

__global__ __launch_bounds__(128) void gemm_band_kernel(
    const float* __restrict__ bq, const float* __restrict__ bk)
{
    extern __shared__ char dsm[];
    float (*Cst)[CLD] = (float(*)[CLD])dsm;                 // reuses stages after MMAs
    float* bqs = (float*)(dsm + SMEM_BIAS_OFF);
    float* bks = bqs + DQ;

    const int h  = blockIdx.x;           // head 0..7
    const int m  = blockIdx.y;           // token tile 0..63
    const int tid  = threadIdx.x;        // 0..127
    const int warp = tid >> 5;           // 0..3
    const int lane = tid & 31;
    const int wm = warp & 1;             // 2 warps along M
    const int wn = warp >> 1;            // 2 warps along N

    // head-sliced biases into smem
    if (tid < DQ)        bqs[tid] = bq[h*DQ + tid];
    else                 bks[tid - DQ] = bk[h*DQ + (tid - DQ)];

    wmma::fragment<wmma::accumulator,16,16,16,float> acc[2][4];
    #pragma unroll
    for (int mm = 0; mm < 2; mm++)
        #pragma unroll
        for (int nn = 0; nn < 4; nn++)
            wmma::fill_fragment(acc[mm][nn], 0.0f);

    // load mapping: A 64x32 bf16 = 256 uint4-groups (2/thr); B 128x32 = 512 (4/thr)
    int rAj[2], cAj[2];
    #pragma unroll
    for (int j = 0; j < 2; j++) { int idx = tid + 128*j; rAj[j] = idx >> 2; cAj[j] = (idx & 3) * 8; }
    int rBj[4], cBj[4];
    const __nv_bfloat16* srcB[4];
    #pragma unroll
    for (int j = 0; j < 4; j++) {
        int idx = tid + 128*j; rBj[j] = idx >> 2; cBj[j] = (idx & 3) * 8;
        int r = rBj[j];
        int wrow = (r < DQ) ? (h*DQ + r) : (DM + h*DQ + (r - DQ));
        srcB[j] = &g_Bbf[(size_t)wrow * DM];
    }
    const __nv_bfloat16* srcA = &g_Abf[(size_t)(m*BM) * DM];

    // per-thread smem dst addresses (stage-relative, as u32)
    unsigned dsmS = (unsigned)__cvta_generic_to_shared(dsm);
    unsigned dstA[2], dstB[4];
    #pragma unroll
    for (int j = 0; j < 2; j++) dstA[j] = dsmS + AS_OFF + (rAj[j]*KPAD + cAj[j]) * 2;
    #pragma unroll
    for (int j = 0; j < 4; j++) dstB[j] = dsmS + BS_OFF + (rBj[j]*KPAD + cBj[j]) * 2;

    const int NIT = DM / BKK;  // 16

    // preload stages 0..NSTAGE-2
    #pragma unroll
    for (int s = 0; s < NSTAGE-1; s++) {
        const int kg = s * BKK;
        const unsigned so = s * STAGE_BYTES;
        #pragma unroll
        for (int j = 0; j < 2; j++)
            CP_ASYNC16(dstA[j] + so, srcA + (size_t)rAj[j]*DM + kg + cAj[j]);
        #pragma unroll
        for (int j = 0; j < 4; j++)
            CP_ASYNC16(dstB[j] + so, srcB[j] + kg + cBj[j]);
        CP_COMMIT();
    }

    for (int kt = 0; kt < NIT; kt++) {
        CP_WAIT2();                 // stage kt landed (3 groups were ahead of it)
        __syncthreads();            // everyone past reading stage (kt-1)%4 == (kt+3)%4

        // issue stage kt+3 (or an empty group to keep the count uniform)
        if (kt + NSTAGE - 1 < NIT) {
            const int kg = (kt + NSTAGE - 1) * BKK;
            const unsigned so = ((kt + NSTAGE - 1) % NSTAGE) * STAGE_BYTES;
            #pragma unroll
            for (int j = 0; j < 2; j++)
                CP_ASYNC16(dstA[j] + so, srcA + (size_t)rAj[j]*DM + kg + cAj[j]);
            #pragma unroll
            for (int j = 0; j < 4; j++)
                CP_ASYNC16(dstB[j] + so, srcB[j] + kg + cBj[j]);
        }
        CP_COMMIT();

        const char* stg = dsm + (kt % NSTAGE) * STAGE_BYTES;
        const __nv_bfloat16 (*As)[KPAD] = (const __nv_bfloat16(*)[KPAD])(stg + AS_OFF);
        const __nv_bfloat16 (*Bs)[KPAD] = (const __nv_bfloat16(*)[KPAD])(stg + BS_OFF);

        #pragma unroll
        for (int kk = 0; kk < BKK; kk += 16) {
            wmma::fragment<wmma::matrix_a,16,16,16,__nv_bfloat16,wmma::row_major> af[2];
            wmma::fragment<wmma::matrix_b,16,16,16,__nv_bfloat16,wmma::col_major> bf[4];
            #pragma unroll
            for (int mm = 0; mm < 2; mm++)
                wmma::load_matrix_sync(af[mm], &As[wm*32 + mm*16][kk], KPAD);
            #pragma unroll
            for (int nn = 0; nn < 4; nn++)
                wmma::load_matrix_sync(bf[nn], &Bs[wn*64 + nn*16][kk], KPAD);
            #pragma unroll
            for (int mm = 0; mm < 2; mm++)
                #pragma unroll
                for (int nn = 0; nn < 4; nn++)
                    wmma::mma_sync(acc[mm][nn], af[mm], bf[nn], acc[mm][nn]);
        }
    }
    CP_WAIT0();
    __syncthreads();   // all warps done with stages before Cst overwrite

    // ---- stage C into smem ----
    #pragma unroll
    for (int mm = 0; mm < 2; mm++)
        #pragma unroll
        for (int nn = 0; nn < 4; nn++)
            wmma::store_matrix_sync(&Cst[wm*32 + mm*16][wn*64 + nn*16],
                                    acc[mm][nn], CLD, wmma::mem_row_major);
    __syncthreads();

    // ---- halo: biased q/k vectors at tile edges (rows 0 and 63) ----
    {
        int hm = (h*NTILE + m)*DQ;
        if (tid < DQ) {
            int d = tid;
            g_qF[hm + d] = Cst[0][d]      + bqs[d];
            g_kF[hm + d] = Cst[0][DQ + d] + bks[d];
        } else {
            int d = tid - DQ;
            g_qL[hm + d] = Cst[BM-1][d]      + bqs[d];
            g_kL[hm + d] = Cst[BM-1][DQ + d] + bks[d];
        }
    }

    // ---- interior banded dots: warp w -> rows w*16 .. w*16+15 ----
    const int d = lane * 2;
    float2 bqv = *(float2*)&bqs[d];
    float2 bkv = *(float2*)&bks[d];
    #pragma unroll
    for (int rr = 0; rr < 16; rr++) {
        int r = warp*16 + rr;
        float2 qv = *(float2*)&Cst[r][d];
        float q0 = qv.x + bqv.x, q1 = qv.y + bqv.y;
        float sf = 0.f, sb = 0.f;
        if (r < BM-1) {
            float2 kv = *(float2*)&Cst[r+1][DQ + d];
            sf = q0*(kv.x + bkv.x) + q1*(kv.y + bkv.y);
        }
        if (r > 0) {
            float2 kv = *(float2*)&Cst[r-1][DQ + d];
            sb = q0*(kv.x + bkv.x) + q1*(kv.y + bkv.y);
        }
        #pragma unroll
        for (int off = 16; off; off >>= 1) {
            sf += __shfl_down_sync(0xffffffffu, sf, off);
            sb += __shfl_down_sync(0xffffffffu, sb, off);
        }
        if (lane == 0) {
            int row = m*BM + r;
            int b = row >> 10;
            int i = row & (SEQ - 1);
            int idx = (b*NH + h)*SEQ + i;
            if (r < BM-1) g_Sf[idx] = sf * (1.0f / DM);
            if (r > 0)    g_Sb[idx] = sb * (1.0f / DM);
        }
    }
}

// -------------------- Kernel 2: boundary dots + softmax + prefix scan ----------
__global__ __launch_bounds__(1024) void scan_kernel(const int* __restrict__ amask)
{
    int bh = blockIdx.x;                 // 0..31
    int b  = bh >> 3;
    int h  = bh & 7;
    int t  = threadIdx.x;                // 0..1023
    int lane = t & 31, wid = t >> 5;

    __shared__ float b_sh[SEQ];
    __shared__ float wsum[32];
    __shared__ float sf_fix[TPB], sb_fix[TPB];

    // tile-boundary dots: warps 0..14 fwd (j=wid), warps 16..30 bwd (j=wid-15)
    if (wid < TPB-1) {
        int mm = b*TPB + wid;            // fwd at token t=64*wid+63
        float acc = 0.f;
        #pragma unroll
        for (int d = lane; d < DQ; d += 32)
            acc += g_qL[(h*NTILE + mm)*DQ + d] * g_kF[(h*NTILE + mm + 1)*DQ + d];
        #pragma unroll
        for (int off = 16; off; off >>= 1) acc += __shfl_down_sync(0xffffffffu, acc, off);
        if (lane == 0) sf_fix[wid] = acc * (1.0f / DM);
    } else if (wid >= 16 && wid < 16 + TPB-1) {
        int j = wid - 15;                // bwd at token t=64*j
        int mm = b*TPB + j;
        float acc = 0.f;
        #pragma unroll
        for (int d = lane; d < DQ; d += 32)
            acc += g_qF[(h*NTILE + mm)*DQ + d] * g_kL[(h*NTILE + mm - 1)*DQ + d];
        #pragma unroll
        for (int off = 16; off; off >>= 1) acc += __shfl_down_sync(0xffffffffu, acc, off);
        if (lane == 0) sb_fix[j] = acc * (1.0f / DM);
    }
    __syncthreads();

    float sf = g_Sf[bh*SEQ + t];
    float sb = g_Sb[bh*SEQ + t];
    if ((t & 63) == 63 && t < SEQ-1) sf = sf_fix[t >> 6];
    if ((t & 63) == 0  && t > 0)     sb = sb_fix[t >> 6];

    bool vf = (t < SEQ-1) && (amask[b*SEQ + t + 1] != 0);
    bool vb = (t > 0)     && (amask[b*SEQ + t - 1] != 0);

    float a, bb;
    if (vf | vb) {
        float mx = fmaxf(vf ? sf : -3.4e38f, vb ? sb : -3.4e38f);
        float ea = vf ? __expf(sf - mx) : 0.f;
        float eb = vb ? __expf(sb - mx) : 0.f;
        float den = ea + eb;
        a  = ea / den;
        bb = eb / den;
    } else {
        a = bb = 1.0f / SEQ;
    }
    b_sh[t] = bb;
    __syncthreads();

    float g = 0.f;
    if (t < SEQ-1) {
        float ph = sqrtf(a * b_sh[t+1] + 1e-9f);
        g_band[bh*SEQ + t] = ph;
        g = logf(ph + 1e-9f);
    }

    float incl = g;
    #pragma unroll
    for (int off = 1; off < 32; off <<= 1) {
        float n = __shfl_up_sync(0xffffffffu, incl, off);
        if (lane >= off) incl += n;
    }
    if (lane == 31) wsum[wid] = incl;
    __syncthreads();
    if (wid == 0) {
        float w = wsum[lane];
        #pragma unroll
        for (int off = 1; off < 32; off <<= 1) {
            float n = __shfl_up_sync(0xffffffffu, w, off);
            if (lane >= off) w += n;
        }
        wsum[lane] = w;
    }
    __syncthreads();
    float base = (wid > 0) ? wsum[wid-1] : 0.f;
    g_G[bh*SEQ + t] = base + incl - g;   // exclusive prefix
}

// -------------------- Kernel 3: materialize outputs (8 rows per block) ---------
__global__ __launch_bounds__(256) void out_kernel(float* __restrict__ out, int write_ph)
{
    const float SQRT_EPS = 3.1622776601683795e-5f;
    const float EPS = 1e-9f;

    int blk = blockIdx.x;                // bh*128 + rowTile
    int bh  = blk >> 7;
    int r0  = (blk & 127) << 3;          // first row i of 8
    int k0  = threadIdx.x << 2;

    const float* Gp = g_G + bh*SEQ;

    __shared__ float Gi_s[8];
    __shared__ float band_s[9];          // band[r0-1 .. r0+7]
    if (threadIdx.x < 8) Gi_s[threadIdx.x] = Gp[r0 + threadIdx.x];
    if (threadIdx.x < 9) {
        int ib = r0 - 1 + threadIdx.x;
        band_s[threadIdx.x] = (ib >= 0 && ib < SEQ-1) ? g_band[bh*SEQ + ib] : 0.f;
    }
    __syncthreads();

    float4 gk = *(const float4*)&Gp[k0];
    size_t base = (size_t)(bh*SEQ + r0) * SEQ + k0;
    size_t pbase = (size_t)NBH*SEQ*SEQ + base;

    #pragma unroll
    for (int r = 0; r < 8; r++) {
        int i = r0 + r;
        float Gi = Gi_s[r];
        float4 o;
        int k;
        k = k0 + 0; o.x = (k == i) ? SQRT_EPS : (__expf((k > i) ? gk.x - Gi : Gi - gk.x) + EPS);
        k = k0 + 1; o.y = (k == i) ? SQRT_EPS : (__expf((k > i) ? gk.y - Gi : Gi - gk.y) + EPS);
        k = k0 + 2; o.z = (k == i) ? SQRT_EPS : (__expf((k > i) ? gk.z - Gi : Gi - gk.z) + EPS);
        k = k0 + 3; o.w = (k == i) ? SQRT_EPS : (__expf((k > i) ? gk.w - Gi : Gi - gk.w) + EPS);
        __stcs((float4*)(out + base + (size_t)r*SEQ), o);

        if (write_ph) {
            float4 p = make_float4(SQRT_EPS, SQRT_EPS, SQRT_EPS, SQRT_EPS);
            int d = (i - 1) - k0;
            if (d >= 0 && d < 4) {
                float v = band_s[r];
                if (d == 0) p.x = v; else if (d == 1) p.y = v; else if (d == 2) p.z = v; else p.w = v;
            }
            d = (i + 1) - k0;
            if (d >= 0 && d < 4) {
                float v = band_s[r + 1];
                if (d == 0) p.x = v; else if (d == 1) p.y = v; else if (d == 2) p.z = v; else p.w = v;
            }
            __stcs((float4*)(out + pbase + (size_t)r*SEQ), p);
        }
    }
}

// -------------------- launch ---------------------------------------------------
extern "C" void kernel_launch(void* const* d_in, const int* in_sizes, int n_in,
                              void* d_out, int out_size)
{
    const float* ctx   = (const float*)d_in[0];   // (4,1024,512) fp32
    const int*   amask = (const int*)  d_in[1];   // (4,1024) int32
    const float* Wq    = (const float*)d_in[2];   // (512,512)
    const float* bq    = (const float*)d_in[3];   // (512,)
    const float* Wk    = (const float*)d_in[4];   // (512,512)
    const float* bk    = (const float*)d_in[5];   // (512,)
    float* out = (float*)d_out;

    long long total = (long long)NBH * SEQ * SEQ;
    int write_ph = ((long long)out_size >= 2 * total) ? 1 : 0;

    cudaFuncSetAttribute(gemm_band_kernel,
                         cudaFuncAttributeMaxDynamicSharedMemorySize, SMEM_TOTAL_GEMM);

    const int CVT_G = (M_TOT*DM + 2*DM*DM) / 8;   // 327680 groups
    cvt_kernel<<<(CVT_G + 255) / 256, 256>>>(ctx, Wq, Wk);

    dim3 ggrid(NH, NTILE);               // (8, 64)
    gemm_band_kernel<<<ggrid, 128, SMEM_TOTAL_GEMM>>>(bq, bk);
    scan_kernel<<<NBH, 1024>>>(amask);
    out_kernel<<<NBH * SEQ / 8, 256>>>(out, write_ph);
}

// round 13
// speedup vs baseline: 1.1007x; 1.0099x over previous
#include <cuda_runtime.h>
#include <cuda_bf16.h>
#include <mma.h>
#include <math.h>

using namespace nvcuda;

// Problem constants (fixed shapes)
#define BSZ   4
#define SEQ   1024
#define DM    512
#define NH    8
#define DQ    64
#define M_TOT (BSZ*SEQ)     // 4096 tokens
#define NBH   (BSZ*NH)      // 32 (batch,head) pairs
#define BM    64            // token tile rows
#define NTILE (M_TOT/BM)    // 64 token tiles
#define TPB   16            // tiles per batch

// -------------------- device scratch --------------------
__device__ __nv_bfloat16 g_Abf[M_TOT * DM];   // 4 MB bf16 ctx
__device__ __nv_bfloat16 g_Bbf[2*DM * DM];    // 1 MB bf16 [Wq;Wk]
__device__ float g_Sf[NBH * SEQ];
__device__ float g_Sb[NBH * SEQ];
__device__ float g_G [NBH * SEQ];
__device__ float g_band[NBH * SEQ];
// halo: biased q/k vectors at tile edges, [head][tile][64]
__device__ float g_qF[NH * NTILE * DQ];
__device__ float g_qL[NH * NTILE * DQ];
__device__ float g_kF[NH * NTILE * DQ];
__device__ float g_kL[NH * NTILE * DQ];

// -------------------- cp.async helpers --------------------
#define CP_ASYNC16(dst_u32, src_ptr) \
    asm volatile("cp.async.cg.shared.global [%0], [%1], 16;\n" :: "r"(dst_u32), "l"(src_ptr))
#define CP_COMMIT() asm volatile("cp.async.commit_group;\n" ::: "memory")
#define CP_WAIT2()  asm volatile("cp.async.wait_group 2;\n" ::: "memory")
#define CP_WAIT0()  asm volatile("cp.async.wait_group 0;\n" ::: "memory")

// -------------------- Kernel 0: fp32 -> bf16 conversion prepass ----------------
__global__ __launch_bounds__(256) void cvt_kernel(
    const float* __restrict__ ctx,
    const float* __restrict__ Wq,
    const float* __restrict__ Wk)
{
    const int CTX_G = (M_TOT * DM) / 8;     // 262144
    const int W_G   = (DM * DM) / 8;        // 32768
    int idx = blockIdx.x * 256 + threadIdx.x;
    if (idx >= CTX_G + 2 * W_G) return;

    const float* src;
    __nv_bfloat16* dst;
    if (idx < CTX_G) {
        src = ctx + (size_t)idx * 8;
        dst = g_Abf + (size_t)idx * 8;
    } else if (idx < CTX_G + W_G) {
        int j = idx - CTX_G;
        src = Wq + (size_t)j * 8;
        dst = g_Bbf + (size_t)j * 8;
    } else {
        int j = idx - CTX_G - W_G;
        src = Wk + (size_t)j * 8;
        dst = g_Bbf + (size_t)(W_G * 8) + (size_t)j * 8;
    }
    float4 v0 = *(const float4*)(src);
    float4 v1 = *(const float4*)(src + 4);
    __nv_bfloat162 b0 = __floats2bfloat162_rn(v0.x, v0.y);
    __nv_bfloat162 b1 = __floats2bfloat162_rn(v0.z, v0.w);
    __nv_bfloat162 b2 = __floats2bfloat162_rn(v1.x, v1.y);
    __nv_bfloat162 b3 = __floats2bfloat162_rn(v1.z, v1.w);
    uint4 packed;
    packed.x = *(unsigned*)&b0; packed.y = *(unsigned*)&b1;
    packed.z = *(unsigned*)&b2; packed.w = *(unsigned*)&b3;
    *(uint4*)dst = packed;
}

// -------------------- Kernel 1: fused GEMM + banded-dot epilogue ---------------
// Block (h, m): C[64 tokens of tile m][ Qh feats 0..63 | Kh feats 64..127 ]
// 256 threads = 8 warps; warp tile 32x32 (wm in {0,1}, wn in {0..3})
#define BN   128
#define BKK  32
#define KPAD 40
#define NSTAGE 4
#define STAGE_BYTES ((BM + BN) * KPAD * 2)       // 15360 per stage
#define AS_OFF      0
#define BS_OFF      (BM * KPAD * 2)              // 5120 within stage
#define CLD  132
#define SMEM_CST_BYTES (BM * CLD * 4)            // 33792
#define SMEM_BIAS_OFF  (NSTAGE * STAGE_BYTES)    // 61440
#define SMEM_TOTAL_GEMM (SMEM_BIAS_OFF + 512)    // 61952

__global__ __launch_bounds__(256) void gemm_band_kernel(
    const float* __restrict__ bq, const float* __restrict__ bk)
{
    extern __shared__ char dsm[];
    float (*Cst)[CLD] = (float(*)[CLD])dsm;                 // reuses stages after MMAs
    float* bqs = (float*)(dsm + SMEM_BIAS_OFF);
    float* bks = bqs + DQ;

    const int h  = blockIdx.x;           // head 0..7
    const int m  = blockIdx.y;           // token tile 0..63
    const int tid  = threadIdx.x;        // 0..255
    const int warp = tid >> 5;           // 0..7
    const int lane = tid & 31;
    const int wm = warp & 1;             // 2 warps along M (32 rows)
    const int wn = warp >> 1;            // 4 warps along N (32 cols)

    // head-sliced biases into smem
    if (tid < DQ)             bqs[tid] = bq[h*DQ + tid];
    else if (tid < 2*DQ)      bks[tid - DQ] = bk[h*DQ + (tid - DQ)];

    wmma::fragment<wmma::accumulator,16,16,16,float> acc[2][2];
    #pragma unroll
    for (int mm = 0; mm < 2; mm++)
        #pragma unroll
        for (int nn = 0; nn < 2; nn++)
            wmma::fill_fragment(acc[mm][nn], 0.0f);

    // load mapping: A 64x32 bf16 = 256 uint4-groups (1/thr); B 128x32 = 512 (2/thr)
    const int rA = tid >> 2, cA = (tid & 3) * 8;
    int rBj[2], cBj[2];
    const __nv_bfloat16* srcB[2];
    #pragma unroll
    for (int j = 0; j < 2; j++) {
        int idx = tid + 256*j; rBj[j] = idx >> 2; cBj[j] = (idx & 3) * 8;
        int r = rBj[j];
        int wrow = (r < DQ) ? (h*DQ + r) : (DM + h*DQ + (r - DQ));
        srcB[j] = &g_Bbf[(size_t)wrow * DM];
    }
    const __nv_bfloat16* srcA = &g_Abf[(size_t)(m*BM) * DM];

    unsigned dsmS = (unsigned)__cvta_generic_to_shared(dsm);
    unsigned dstA = dsmS + AS_OFF + (rA*KPAD + cA) * 2;
    unsigned dstB[2];
    #pragma unroll
    for (int j = 0; j < 2; j++) dstB[j] = dsmS + BS_OFF + (rBj[j]*KPAD + cBj[j]) * 2;

    const int NIT = DM / BKK;  // 16

    // preload stages 0..NSTAGE-2
    #pragma unroll
    for (int s = 0; s < NSTAGE-1; s++) {
        const int kg = s * BKK;
        const unsigned so = s * STAGE_BYTES;
        CP_ASYNC16(dstA + so, srcA + (size_t)rA*DM + kg + cA);
        #pragma unroll
        for (int j = 0; j < 2; j++)
            CP_ASYNC16(dstB[j] + so, srcB[j] + kg + cBj[j]);
        CP_COMMIT();
    }

    for (int kt = 0; kt < NIT; kt++) {
        CP_WAIT2();                 // stage kt landed
        __syncthreads();

        if (kt + NSTAGE - 1 < NIT) {
            const int kg = (kt + NSTAGE - 1) * BKK;
            const unsigned so = ((kt + NSTAGE - 1) % NSTAGE) * STAGE_BYTES;
            CP_ASYNC16(dstA + so, srcA + (size_t)rA*DM + kg + cA);
            #pragma unroll
            for (int j = 0; j < 2; j++)
                CP_ASYNC16(dstB[j] + so, srcB[j] + kg + cBj[j]);
        }
        CP_COMMIT();

        const char* stg = dsm + (kt % NSTAGE) * STAGE_BYTES;
        const __nv_bfloat16 (*As)[KPAD] = (const __nv_bfloat16(*)[KPAD])(stg + AS_OFF);
        const __nv_bfloat16 (*Bs)[KPAD] = (const __nv_bfloat16(*)[KPAD])(stg + BS_OFF);

        #pragma unroll
        for (int kk = 0; kk < BKK; kk += 16) {
            wmma::fragment<wmma::matrix_a,16,16,16,__nv_bfloat16,wmma::row_major> af[2];
            wmma::fragment<wmma::matrix_b,16,16,16,__nv_bfloat16,wmma::col_major> bf[2];
            #pragma unroll
            for (int mm = 0; mm < 2; mm++)
                wmma::load_matrix_sync(af[mm], &As[wm*32 + mm*16][kk], KPAD);
            #pragma unroll
            for (int nn = 0; nn < 2; nn++)
                wmma::load_matrix_sync(bf[nn], &Bs[wn*32 + nn*16][kk], KPAD);
            #pragma unroll
            for (int mm = 0; mm < 2; mm++)
                #pragma unroll
                for (int nn = 0; nn < 2; nn++)
                    wmma::mma_sync(acc[mm][nn], af[mm], bf[nn], acc[mm][nn]);
        }
    }
    CP_WAIT0();
    __syncthreads();   // all warps done with stages before Cst overwrite

    // ---- stage C into smem ----
    #pragma unroll
    for (int mm = 0; mm < 2; mm++)
        #pragma unroll
        for (int nn = 0; nn < 2; nn++)
            wmma::store_matrix_sync(&Cst[wm*32 + mm*16][wn*32 + nn*16],
                                    acc[mm][nn], CLD, wmma::mem_row_major);
    __syncthreads();

    // ---- halo: biased q/k vectors at tile edges (rows 0 and 63) ----
    {
        int hm = (h*NTILE + m)*DQ;
        if (tid < DQ) {
            int d = tid;
            g_qF[hm + d] = Cst[0][d]      + bqs[d];
            g_kF[hm + d] = Cst[0][DQ + d] + bks[d];
        } else if (tid < 2*DQ) {
            int d = tid - DQ;
            g_qL[hm + d] = Cst[BM-1][d]      + bqs[d];
            g_kL[hm + d] = Cst[BM-1][DQ + d] + bks[d];
        }
    }

    // ---- interior banded dots: warp w -> rows w*8 .. w*8+7 ----
    const int d = lane * 2;
    float2 bqv = *(float2*)&bqs[d];
    float2 bkv = *(float2*)&bks[d];
    #pragma unroll
    for (int rr = 0; rr < 8; rr++) {
        int r = warp*8 + rr;
        float2 qv = *(float2*)&Cst[r][d];
        float q0 = qv.x + bqv.x, q1 = qv.y + bqv.y;
        float sf = 0.f, sb = 0.f;
        if (r < BM-1) {
            float2 kv = *(float2*)&Cst[r+1][DQ + d];
            sf = q0*(kv.x + bkv.x) + q1*(kv.y + bkv.y);
        }
        if (r > 0) {
            float2 kv = *(float2*)&Cst[r-1][DQ + d];
            sb = q0*(kv.x + bkv.x) + q1*(kv.y + bkv.y);
        }
        #pragma unroll
        for (int off = 16; off; off >>= 1) {
            sf += __shfl_down_sync(0xffffffffu, sf, off);
            sb += __shfl_down_sync(0xffffffffu, sb, off);
        }
        if (lane == 0) {
            int row = m*BM + r;
            int b = row >> 10;
            int i = row & (SEQ - 1);
            int idx = (b*NH + h)*SEQ + i;
            if (r < BM-1) g_Sf[idx] = sf * (1.0f / DM);
            if (r > 0)    g_Sb[idx] = sb * (1.0f / DM);
        }
    }
}

// -------------------- Kernel 2: boundary dots + softmax + prefix scan ----------
__global__ __launch_bounds__(1024) void scan_kernel(const int* __restrict__ amask)
{
    int bh = blockIdx.x;                 // 0..31
    int b  = bh >> 3;
    int h  = bh & 7;
    int t  = threadIdx.x;                // 0..1023
    int lane = t & 31, wid = t >> 5;

    __shared__ float b_sh[SEQ];
    __shared__ float wsum[32];
    __shared__ float sf_fix[TPB], sb_fix[TPB];

    // tile-boundary dots: warps 0..14 fwd (j=wid), warps 16..30 bwd (j=wid-15)
    if (wid < TPB-1) {
        int mm = b*TPB + wid;            // fwd at token t=64*wid+63
        float acc = 0.f;
        #pragma unroll
        for (int d = lane; d < DQ; d += 32)
            acc += g_qL[(h*NTILE + mm)*DQ + d] * g_kF[(h*NTILE + mm + 1)*DQ + d];
        #pragma unroll
        for (int off = 16; off; off >>= 1) acc += __shfl_down_sync(0xffffffffu, acc, off);
        if (lane == 0) sf_fix[wid] = acc * (1.0f / DM);
    } else if (wid >= 16 && wid < 16 + TPB-1) {
        int j = wid - 15;                // bwd at token t=64*j
        int mm = b*TPB + j;
        float acc = 0.f;
        #pragma unroll
        for (int d = lane; d < DQ; d += 32)
            acc += g_qF[(h*NTILE + mm)*DQ + d] * g_kL[(h*NTILE + mm - 1)*DQ + d];
        #pragma unroll
        for (int off = 16; off; off >>= 1) acc += __shfl_down_sync(0xffffffffu, acc, off);
        if (lane == 0) sb_fix[j] = acc * (1.0f / DM);
    }
    __syncthreads();

    float sf = g_Sf[bh*SEQ + t];
    float sb = g_Sb[bh*SEQ + t];
    if ((t & 63) == 63 && t < SEQ-1) sf = sf_fix[t >> 6];
    if ((t & 63) == 0  && t > 0)     sb = sb_fix[t >> 6];

    bool vf = (t < SEQ-1) && (amask[b*SEQ + t + 1] != 0);
    bool vb = (t > 0)     && (amask[b*SEQ + t - 1] != 0);

    float a, bb;
    if (vf | vb) {
        float mx = fmaxf(vf ? sf : -3.4e38f, vb ? sb : -3.4e38f);
        float ea = vf ? __expf(sf - mx) : 0.f;
        float eb = vb ? __expf(sb - mx) : 0.f;
        float den = ea + eb;
        a  = ea / den;
        bb = eb / den;
    } else {
        a = bb = 1.0f / SEQ;
    }
    b_sh[t] = bb;
    __syncthreads();

    float g = 0.f;
    if (t < SEQ-1) {
        float ph = sqrtf(a * b_sh[t+1] + 1e-9f);
        g_band[bh*SEQ + t] = ph;
        g = logf(ph + 1e-9f);
    }

    float incl = g;
    #pragma unroll
    for (int off = 1; off < 32; off <<= 1) {
        float n = __shfl_up_sync(0xffffffffu, incl, off);
        if (lane >= off) incl += n;
    }
    if (lane == 31) wsum[wid] = incl;
    __syncthreads();
    if (wid == 0) {
        float w = wsum[lane];
        #pragma unroll
        for (int off = 1; off < 32; off <<= 1) {
            float n = __shfl_up_sync(0xffffffffu, w, off);
            if (lane >= off) w += n;
        }
        wsum[lane] = w;
    }
    __syncthreads();
    float base = (wid > 0) ? wsum[wid-1] : 0.f;
    g_G[bh*SEQ + t] = base + incl - g;   // exclusive prefix
}

// -------------------- Kernel 3: materialize outputs (16 rows per block) --------
// G monotone decreasing (all g<0) => attn[i,k] = exp(-|G_k - G_i|) + eps, k != i.
__global__ __launch_bounds__(256) void out_kernel(float* __restrict__ out, int write_ph)
{
    const float SQRT_EPS = 3.1622776601683795e-5f;
    const float EPS = 1e-9f;

    int blk = blockIdx.x;                // bh*64 + rowTile
    int bh  = blk >> 6;
    int r0  = (blk & 63) << 4;           // first row i of 16
    int k0  = threadIdx.x << 2;

    const float* Gp = g_G + bh*SEQ;

    __shared__ float Gi_s[16];
    __shared__ float band_s[17];         // band[r0-1 .. r0+15]
    if (threadIdx.x < 16) Gi_s[threadIdx.x] = Gp[r0 + threadIdx.x];
    if (threadIdx.x < 17) {
        int ib = r0 - 1 + threadIdx.x;
        band_s[threadIdx.x] = (ib >= 0 && ib < SEQ-1) ? g_band[bh*SEQ + ib] : 0.f;
    }
    __syncthreads();

    float4 gk = *(const float4*)&Gp[k0];
    float* ptr  = out + (size_t)(bh*SEQ + r0) * SEQ + k0;
    float* pptr = ptr + (size_t)NBH*SEQ*SEQ;

    const bool diag_col = ((unsigned)(r0 + 16) > (unsigned)k0) && (k0 + 4 > r0);

    #pragma unroll
    for (int r = 0; r < 16; r++) {
        int i = r0 + r;
        float Gi = Gi_s[r];
        float4 o;
        o.x = __expf(-fabsf(gk.x - Gi)) + EPS;
        o.y = __expf(-fabsf(gk.y - Gi)) + EPS;
        o.z = __expf(-fabsf(gk.z - Gi)) + EPS;
        o.w = __expf(-fabsf(gk.w - Gi)) + EPS;
        if (diag_col) {
            int d = i - k0;
            if (d == 0) o.x = SQRT_EPS; else if (d == 1) o.y = SQRT_EPS;
            else if (d == 2) o.z = SQRT_EPS; else if (d == 3) o.w = SQRT_EPS;
        }
        __stcs((float4*)ptr, o);
        ptr += SEQ;

        if (write_ph) {
            float4 p = make_float4(SQRT_EPS, SQRT_EPS, SQRT_EPS, SQRT_EPS);
            int d = (i - 1) - k0;
            if (d >= 0 && d < 4) {
                float v = band_s[r];
                if (d == 0) p.x = v; else if (d == 1) p.y = v; else if (d == 2) p.z = v; else p.w = v;
            }
            d = (i + 1) - k0;
            if (d >= 0 && d < 4) {
                float v = band_s[r + 1];
                if (d == 0) p.x = v; else if (d == 1) p.y = v; else if (d == 2) p.z = v; else p.w = v;
            }
            __stcs((float4*)pptr, p);
            pptr += SEQ;
        }
    }
}

// -------------------- launch ---------------------------------------------------
extern "C" void kernel_launch(void* const* d_in, const int* in_sizes, int n_in,
                              void* d_out, int out_size)
{
    const float* ctx   = (const float*)d_in[0];   // (4,1024,512) fp32
    const int*   amask = (const int*)  d_in[1];   // (4,1024) int32
    const float* Wq    = (const float*)d_in[2];   // (512,512)
    const float* bq    = (const float*)d_in[3];   // (512,)
    const float* Wk    = (const float*)d_in[4];   // (512,512)
    const float* bk    = (const float*)d_in[5];   // (512,)
    float* out = (float*)d_out;

    long long total = (long long)NBH * SEQ * SEQ;
    int write_ph = ((long long)out_size >= 2 * total) ? 1 : 0;

    cudaFuncSetAttribute(gemm_band_kernel,
                         cudaFuncAttributeMaxDynamicSharedMemorySize, SMEM_TOTAL_GEMM);

    const int CVT_G = (M_TOT*DM + 2*DM*DM) / 8;   // 327680 groups
    cvt_kernel<<<(CVT_G + 255) / 256, 256>>>(ctx, Wq, Wk);

    dim3 ggrid(NH, NTILE);               // (8, 64)
    gemm_band_kernel<<<ggrid, 256, SMEM_TOTAL_GEMM>>>(bq, bk);
    scan_kernel<<<NBH, 1024>>>(amask);
    out_kernel<<<NBH * SEQ / 16, 256>>>(out, write_ph);
}

// round 15
// speedup vs baseline: 1.1242x; 1.0214x over previous
#include <cuda_runtime.h>
#include <cuda_bf16.h>
#include <mma.h>
#include <math.h>

using namespace nvcuda;

// Problem constants (fixed shapes)
#define BSZ   4
#define SEQ   1024
#define DM    512
#define NH    8
#define DQ    64
#define M_TOT (BSZ*SEQ)     // 4096 tokens
#define NBH   (BSZ*NH)      // 32 (batch,head) pairs
#define BM    64            // token tile rows
#define NTILE (M_TOT/BM)    // 64 token tiles
#define TPB   16            // tiles per batch

// -------------------- device scratch --------------------
__device__ __nv_bfloat16 g_Abf[M_TOT * DM];   // 4 MB bf16 ctx
__device__ __nv_bfloat16 g_Bbf[2*DM * DM];    // 1 MB bf16 [Wq;Wk]
__device__ float g_Sf[NBH * SEQ];
__device__ float g_Sb[NBH * SEQ];
__device__ float g_G [NBH * SEQ];
__device__ float g_band[NBH * SEQ];
// halo: biased q/k vectors at tile edges, [head][tile][64]
__device__ float g_qF[NH * NTILE * DQ];
__device__ float g_qL[NH * NTILE * DQ];
__device__ float g_kF[NH * NTILE * DQ];
__device__ float g_kL[NH * NTILE * DQ];

// -------------------- cp.async helpers --------------------
#define CP_ASYNC16(dst_u32, src_ptr) \
    asm volatile("cp.async.cg.shared.global [%0], [%1], 16;\n" :: "r"(dst_u32), "l"(src_ptr))
#define CP_COMMIT() asm volatile("cp.async.commit_group;\n" ::: "memory")
#define CP_WAIT1()  asm volatile("cp.async.wait_group 1;\n" ::: "memory")
#define CP_WAIT0()  asm volatile("cp.async.wait_group 0;\n" ::: "memory")

// -------------------- Kernel 0: fp32 -> bf16 conversion prepass ----------------
__global__ __launch_bounds__(256) void cvt_kernel(
    const float* __restrict__ ctx,
    const float* __restrict__ Wq,
    const float* __restrict__ Wk)
{
    const int CTX_G = (M_TOT * DM) / 8;     // 262144
    const int W_G   = (DM * DM) / 8;        // 32768
    int idx = blockIdx.x * 256 + threadIdx.x;
    if (idx >= CTX_G + 2 * W_G) return;

    const float* src;
    __nv_bfloat16* dst;
    if (idx < CTX_G) {
        src = ctx + (size_t)idx * 8;
        dst = g_Abf + (size_t)idx * 8;
    } else if (idx < CTX_G + W_G) {
        int j = idx - CTX_G;
        src = Wq + (size_t)j * 8;
        dst = g_Bbf + (size_t)j * 8;
    } else {
        int j = idx - CTX_G - W_G;
        src = Wk + (size_t)j * 8;
        dst = g_Bbf + (size_t)(W_G * 8) + (size_t)j * 8;
    }
    float4 v0 = *(const float4*)(src);
    float4 v1 = *(const float4*)(src + 4);
    __nv_bfloat162 b0 = __floats2bfloat162_rn(v0.x, v0.y);
    __nv_bfloat162 b1 = __floats2bfloat162_rn(v0.z, v0.w);
    __nv_bfloat162 b2 = __floats2bfloat162_rn(v1.x, v1.y);
    __nv_bfloat162 b3 = __floats2bfloat162_rn(v1.z, v1.w);
    uint4 packed;
    packed.x = *(unsigned*)&b0; packed.y = *(unsigned*)&b1;
    packed.z = *(unsigned*)&b2; packed.w = *(unsigned*)&b3;
    *(uint4*)dst = packed;
}

// -------------------- Kernel 1: fused GEMM + banded-dot epilogue ---------------
// Block (h, m): C[64 tokens of tile m][ Qh feats 0..63 | Kh feats 64..127 ]
// 256 threads = 8 warps; warp tile 32x32 (wm in {0,1}, wn in {0..3})
// BKK=64: 4 K-steps per barrier interval; 3-stage cp.async ring (2 chunks ahead).
#define BN   128
#define BKK  64
#define KPAD 72
#define NSTAGE 3
#define STAGE_BYTES ((BM + BN) * KPAD * 2)       // 27648 per stage
#define AS_OFF      0
#define BS_OFF      (BM * KPAD * 2)              // 9216 within stage
#define CLD  132
#define SMEM_BIAS_OFF  (NSTAGE * STAGE_BYTES)    // 82944
#define SMEM_TOTAL_GEMM (SMEM_BIAS_OFF + 512)    // 83456

__global__ __launch_bounds__(256) void gemm_band_kernel(
    const float* __restrict__ bq, const float* __restrict__ bk)
{
    extern __shared__ char dsm[];
    float (*Cst)[CLD] = (float(*)[CLD])dsm;                 // reuses stages after MMAs
    float* bqs = (float*)(dsm + SMEM_BIAS_OFF);
    float* bks = bqs + DQ;

    const int h  = blockIdx.x;           // head 0..7
    const int m  = blockIdx.y;           // token tile 0..63
    const int tid  = threadIdx.x;        // 0..255
    const int warp = tid >> 5;           // 0..7
    const int lane = tid & 31;
    const int wm = warp & 1;             // 2 warps along M (32 rows)
    const int wn = warp >> 1;            // 4 warps along N (32 cols)

    // head-sliced biases into smem
    if (tid < DQ)             bqs[tid] = bq[h*DQ + tid];
    else if (tid < 2*DQ)      bks[tid - DQ] = bk[h*DQ + (tid - DQ)];

    wmma::fragment<wmma::accumulator,16,16,16,float> acc[2][2];
    #pragma unroll
    for (int mm = 0; mm < 2; mm++)
        #pragma unroll
        for (int nn = 0; nn < 2; nn++)
            wmma::fill_fragment(acc[mm][nn], 0.0f);

    // load mapping (BKK=64): A 64x64 bf16 = 512 uint4-chunks (2/thr);
    //                        B 128x64     = 1024 chunks (4/thr)
    int rA[2], cA[2];
    #pragma unroll
    for (int j = 0; j < 2; j++) {
        int idx = tid + 256*j;
        rA[j] = idx >> 3; cA[j] = (idx & 7) * 8;
    }
    int rB[4], cB[4];
    const __nv_bfloat16* srcB[4];
    #pragma unroll
    for (int j = 0; j < 4; j++) {
        int idx = tid + 256*j;
        rB[j] = idx >> 3; cB[j] = (idx & 7) * 8;
        int r = rB[j];
        int wrow = (r < DQ) ? (h*DQ + r) : (DM + h*DQ + (r - DQ));
        srcB[j] = &g_Bbf[(size_t)wrow * DM];
    }
    const __nv_bfloat16* srcA = &g_Abf[(size_t)(m*BM) * DM];

    unsigned dsmS = (unsigned)__cvta_generic_to_shared(dsm);
    unsigned dstA[2], dstB[4];
    #pragma unroll
    for (int j = 0; j < 2; j++) dstA[j] = dsmS + AS_OFF + (rA[j]*KPAD + cA[j]) * 2;
    #pragma unroll
    for (int j = 0; j < 4; j++) dstB[j] = dsmS + BS_OFF + (rB[j]*KPAD + cB[j]) * 2;

    #define LOAD_CHUNK(c) do { \
        const int _kg = (c) * BKK; \
        const unsigned _so = ((c) % NSTAGE) * STAGE_BYTES; \
        _Pragma("unroll") \
        for (int j = 0; j < 2; j++) \
            CP_ASYNC16(dstA[j] + _so, srcA + (size_t)rA[j]*DM + _kg + cA[j]); \
        _Pragma("unroll") \
        for (int j = 0; j < 4; j++) \
            CP_ASYNC16(dstB[j] + _so, srcB[j] + _kg + cB[j]); \
    } while(0)

    const int NIT = DM / BKK;  // 8

    // prologue: chunks 0,1
    LOAD_CHUNK(0); CP_COMMIT();
    LOAD_CHUNK(1); CP_COMMIT();

    for (int kt = 0; kt < NIT; kt++) {
        CP_WAIT1();                 // chunk kt landed (1 newer group may be pending)
        __syncthreads();            // all warps done reading slot (kt+2)%3 == (kt-1)%3

        if (kt + 2 < NIT) LOAD_CHUNK(kt + 2);
        CP_COMMIT();                // uniform group count (empty ok)

        const char* stg = dsm + (kt % NSTAGE) * STAGE_BYTES;
        const __nv_bfloat16 (*As)[KPAD] = (const __nv_bfloat16(*)[KPAD])(stg + AS_OFF);
        const __nv_bfloat16 (*Bs)[KPAD] = (const __nv_bfloat16(*)[KPAD])(stg + BS_OFF);

        #pragma unroll
        for (int kk = 0; kk < BKK; kk += 16) {
            wmma::fragment<wmma::matrix_a,16,16,16,__nv_bfloat16,wmma::row_major> af[2];
            wmma::fragment<wmma::matrix_b,16,16,16,__nv_bfloat16,wmma::col_major> bf[2];
            #pragma unroll
            for (int mm = 0; mm < 2; mm++)
                wmma::load_matrix_sync(af[mm], &As[wm*32 + mm*16][kk], KPAD);
            #pragma unroll
            for (int nn = 0; nn < 2; nn++)
                wmma::load_matrix_sync(bf[nn], &Bs[wn*32 + nn*16][kk], KPAD);
            #pragma unroll
            for (int mm = 0; mm < 2; mm++)
                #pragma unroll
                for (int nn = 0; nn < 2; nn++)
                    wmma::mma_sync(acc[mm][nn], af[mm], bf[nn], acc[mm][nn]);
        }
    }
    CP_WAIT0();
    __syncthreads();   // all warps done with stages before Cst overwrite

    // ---- stage C into smem ----
    #pragma unroll
    for (int mm = 0; mm < 2; mm++)
        #pragma unroll
        for (int nn = 0; nn < 2; nn++)
            wmma::store_matrix_sync(&Cst[wm*32 + mm*16][wn*32 + nn*16],
                                    acc[mm][nn], CLD, wmma::mem_row_major);
    __syncthreads();

    // ---- halo: biased q/k vectors at tile edges (rows 0 and 63) ----
    {
        int hm = (h*NTILE + m)*DQ;
        if (tid < DQ) {
            int d = tid;
            g_qF[hm + d] = Cst[0][d]      + bqs[d];
            g_kF[hm + d] = Cst[0][DQ + d] + bks[d];
        } else if (tid < 2*DQ) {
            int d = tid - DQ;
            g_qL[hm + d] = Cst[BM-1][d]      + bqs[d];
            g_kL[hm + d] = Cst[BM-1][DQ + d] + bks[d];
        }
    }

    // ---- interior banded dots: warp w -> rows w*8 .. w*8+7 ----
    const int d = lane * 2;
    float2 bqv = *(float2*)&bqs[d];
    float2 bkv = *(float2*)&bks[d];
    #pragma unroll
    for (int rr = 0; rr < 8; rr++) {
        int r = warp*8 + rr;
        float2 qv = *(float2*)&Cst[r][d];
        float q0 = qv.x + bqv.x, q1 = qv.y + bqv.y;
        float sf = 0.f, sb = 0.f;
        if (r < BM-1) {
            float2 kv = *(float2*)&Cst[r+1][DQ + d];
            sf = q0*(kv.x + bkv.x) + q1*(kv.y + bkv.y);
        }
        if (r > 0) {
            float2 kv = *(float2*)&Cst[r-1][DQ + d];
            sb = q0*(kv.x + bkv.x) + q1*(kv.y + bkv.y);
        }
        #pragma unroll
        for (int off = 16; off; off >>= 1) {
            sf += __shfl_down_sync(0xffffffffu, sf, off);
            sb += __shfl_down_sync(0xffffffffu, sb, off);
        }
        if (lane == 0) {
            int row = m*BM + r;
            int b = row >> 10;
            int i = row & (SEQ - 1);
            int idx = (b*NH + h)*SEQ + i;
            if (r < BM-1) g_Sf[idx] = sf * (1.0f / DM);
            if (r > 0)    g_Sb[idx] = sb * (1.0f / DM);
        }
    }
}

// -------------------- Kernel 2: boundary dots + softmax + prefix scan ----------
__global__ __launch_bounds__(1024) void scan_kernel(const int* __restrict__ amask)
{
    int bh = blockIdx.x;                 // 0..31
    int b  = bh >> 3;
    int h  = bh & 7;
    int t  = threadIdx.x;                // 0..1023
    int lane = t & 31, wid = t >> 5;

    __shared__ float b_sh[SEQ];
    __shared__ float wsum[32];
    __shared__ float sf_fix[TPB], sb_fix[TPB];

    // tile-boundary dots: warps 0..14 fwd (j=wid), warps 16..30 bwd (j=wid-15)
    if (wid < TPB-1) {
        int mm = b*TPB + wid;            // fwd at token t=64*wid+63
        float acc = 0.f;
        #pragma unroll
        for (int d = lane; d < DQ; d += 32)
            acc += g_qL[(h*NTILE + mm)*DQ + d] * g_kF[(h*NTILE + mm + 1)*DQ + d];
        #pragma unroll
        for (int off = 16; off; off >>= 1) acc += __shfl_down_sync(0xffffffffu, acc, off);
        if (lane == 0) sf_fix[wid] = acc * (1.0f / DM);
    } else if (wid >= 16 && wid < 16 + TPB-1) {
        int j = wid - 15;                // bwd at token t=64*j
        int mm = b*TPB + j;
        float acc = 0.f;
        #pragma unroll
        for (int d = lane; d < DQ; d += 32)
            acc += g_qF[(h*NTILE + mm)*DQ + d] * g_kL[(h*NTILE + mm - 1)*DQ + d];
        #pragma unroll
        for (int off = 16; off; off >>= 1) acc += __shfl_down_sync(0xffffffffu, acc, off);
        if (lane == 0) sb_fix[j] = acc * (1.0f / DM);
    }
    __syncthreads();

    float sf = g_Sf[bh*SEQ + t];
    float sb = g_Sb[bh*SEQ + t];
    if ((t & 63) == 63 && t < SEQ-1) sf = sf_fix[t >> 6];
    if ((t & 63) == 0  && t > 0)     sb = sb_fix[t >> 6];

    bool vf = (t < SEQ-1) && (amask[b*SEQ + t + 1] != 0);
    bool vb = (t > 0)     && (amask[b*SEQ + t - 1] != 0);

    float a, bb;
    if (vf | vb) {
        float mx = fmaxf(vf ? sf : -3.4e38f, vb ? sb : -3.4e38f);
        float ea = vf ? __expf(sf - mx) : 0.f;
        float eb = vb ? __expf(sb - mx) : 0.f;
        float den = ea + eb;
        a  = ea / den;
        bb = eb / den;
    } else {
        a = bb = 1.0f / SEQ;
    }
    b_sh[t] = bb;
    __syncthreads();

    float g = 0.f;
    if (t < SEQ-1) {
        float ph = sqrtf(a * b_sh[t+1] + 1e-9f);
        g_band[bh*SEQ + t] = ph;
        g = logf(ph + 1e-9f);
    }

    float incl = g;
    #pragma unroll
    for (int off = 1; off < 32; off <<= 1) {
        float n = __shfl_up_sync(0xffffffffu, incl, off);
        if (lane >= off) incl += n;
    }
    if (lane == 31) wsum[wid] = incl;
    __syncthreads();
    if (wid == 0) {
        float w = wsum[lane];
        #pragma unroll
        for (int off = 1; off < 32; off <<= 1) {
            float n = __shfl_up_sync(0xffffffffu, w, off);
            if (lane >= off) w += n;
        }
        wsum[lane] = w;
    }
    __syncthreads();
    float base = (wid > 0) ? wsum[wid-1] : 0.f;
    g_G[bh*SEQ + t] = base + incl - g;   // exclusive prefix
}

// -------------------- Kernel 3: materialize outputs (16 rows per block) --------
// G monotone decreasing (all g<0) => attn[i,k] = exp(-|G_k - G_i|) + eps, k != i.
__global__ __launch_bounds__(256) void out_kernel(float* __restrict__ out, int write_ph)
{
    const float SQRT_EPS = 3.1622776601683795e-5f;
    const float EPS = 1e-9f;

    int blk = blockIdx.x;                // bh*64 + rowTile
    int bh  = blk >> 6;
    int r0  = (blk & 63) << 4;           // first row i of 16
    int k0  = threadIdx.x << 2;

    const float* Gp = g_G + bh*SEQ;

    __shared__ float Gi_s[16];
    __shared__ float band_s[17];         // band[r0-1 .. r0+15]
    if (threadIdx.x < 16) Gi_s[threadIdx.x] = Gp[r0 + threadIdx.x];
    if (threadIdx.x < 17) {
        int ib = r0 - 1 + threadIdx.x;
        band_s[threadIdx.x] = (ib >= 0 && ib < SEQ-1) ? g_band[bh*SEQ + ib] : 0.f;
    }
    __syncthreads();

    float4 gk = *(const float4*)&Gp[k0];
    float* ptr  = out + (size_t)(bh*SEQ + r0) * SEQ + k0;
    float* pptr = ptr + (size_t)NBH*SEQ*SEQ;

    const bool diag_col = ((unsigned)(r0 + 16) > (unsigned)k0) && (k0 + 4 > r0);

    #pragma unroll
    for (int r = 0; r < 16; r++) {
        int i = r0 + r;
        float Gi = Gi_s[r];
        float4 o;
        o.x = __expf(-fabsf(gk.x - Gi)) + EPS;
        o.y = __expf(-fabsf(gk.y - Gi)) + EPS;
        o.z = __expf(-fabsf(gk.z - Gi)) + EPS;
        o.w = __expf(-fabsf(gk.w - Gi)) + EPS;
        if (diag_col) {
            int d = i - k0;
            if (d == 0) o.x = SQRT_EPS; else if (d == 1) o.y = SQRT_EPS;
            else if (d == 2) o.z = SQRT_EPS; else if (d == 3) o.w = SQRT_EPS;
        }
        __stcs((float4*)ptr, o);
        ptr += SEQ;

        if (write_ph) {
            float4 p = make_float4(SQRT_EPS, SQRT_EPS, SQRT_EPS, SQRT_EPS);
            int d = (i - 1) - k0;
            if (d >= 0 && d < 4) {
                float v = band_s[r];
                if (d == 0) p.x = v; else if (d == 1) p.y = v; else if (d == 2) p.z = v; else p.w = v;
            }
            d = (i + 1) - k0;
            if (d >= 0 && d < 4) {
                float v = band_s[r + 1];
                if (d == 0) p.x = v; else if (d == 1) p.y = v; else if (d == 2) p.z = v; else p.w = v;
            }
            __stcs((float4*)pptr, p);
            pptr += SEQ;
        }
    }
}

// -------------------- launch ---------------------------------------------------
extern "C" void kernel_launch(void* const* d_in, const int* in_sizes, int n_in,
                              void* d_out, int out_size)
{
    const float* ctx   = (const float*)d_in[0];   // (4,1024,512) fp32
    const int*   amask = (const int*)  d_in[1];   // (4,1024) int32
    const float* Wq    = (const float*)d_in[2];   // (512,512)
    const float* bq    = (const float*)d_in[3];   // (512,)
    const float* Wk    = (const float*)d_in[4];   // (512,512)
    const float* bk    = (const float*)d_in[5];   // (512,)
    float* out = (float*)d_out;

    long long total = (long long)NBH * SEQ * SEQ;
    int write_ph = ((long long)out_size >= 2 * total) ? 1 : 0;

    cudaFuncSetAttribute(gemm_band_kernel,
                         cudaFuncAttributeMaxDynamicSharedMemorySize, SMEM_TOTAL_GEMM);

    const int CVT_G = (M_TOT*DM + 2*DM*DM) / 8;   // 327680 groups
    cvt_kernel<<<(CVT_G + 255) / 256, 256>>>(ctx, Wq, Wk);

    dim3 ggrid(NH, NTILE);               // (8, 64)
    gemm_band_kernel<<<ggrid, 256, SMEM_TOTAL_GEMM>>>(bq, bk);
    scan_kernel<<<NBH, 1024>>>(amask);
    out_kernel<<<NBH * SEQ / 16, 256>>>(out, write_ph);
}

// round 16
// speedup vs baseline: 1.1833x; 1.0526x over previous
#include <cuda_runtime.h>
#include <cuda_bf16.h>
#include <mma.h>
#include <math.h>

using namespace nvcuda;

// Problem constants (fixed shapes)
#define BSZ   4
#define SEQ   1024
#define DM    512
#define NH    8
#define DQ    64
#define M_TOT (BSZ*SEQ)     // 4096 tokens
#define NBH   (BSZ*NH)      // 32 (batch,head) pairs
#define BM    64            // token tile rows
#define NTILE (M_TOT/BM)    // 64 token tiles
#define TPB   16            // tiles per batch
#define TOTAL ((size_t)NBH * SEQ * SEQ)   // 33,554,432 elements per tensor

// -------------------- device scratch --------------------
__device__ __nv_bfloat16 g_Abf[M_TOT * DM];   // 4 MB bf16 ctx
__device__ __nv_bfloat16 g_Bbf[2*DM * DM];    // 1 MB bf16 [Wq;Wk]
__device__ float g_Sf[NBH * SEQ];
__device__ float g_Sb[NBH * SEQ];
__device__ float g_G [NBH * SEQ];
__device__ float g_band[NBH * SEQ];
// halo: biased q/k vectors at tile edges, [head][tile][64]
__device__ float g_qF[NH * NTILE * DQ];
__device__ float g_qL[NH * NTILE * DQ];
__device__ float g_kF[NH * NTILE * DQ];
__device__ float g_kL[NH * NTILE * DQ];

// -------------------- cp.async helpers --------------------
#define CP_ASYNC16(dst_u32, src_ptr) \
    asm volatile("cp.async.cg.shared.global [%0], [%1], 16;\n" :: "r"(dst_u32), "l"(src_ptr))
#define CP_COMMIT() asm volatile("cp.async.commit_group;\n" ::: "memory")
#define CP_WAIT1()  asm volatile("cp.async.wait_group 1;\n" ::: "memory")
#define CP_WAIT0()  asm volatile("cp.async.wait_group 0;\n" ::: "memory")

// -------------------- Kernel 0: fp32 -> bf16 conversion prepass ----------------
__global__ __launch_bounds__(256) void cvt_kernel(
    const float* __restrict__ ctx,
    const float* __restrict__ Wq,
    const float* __restrict__ Wk)
{
    const int CTX_G = (M_TOT * DM) / 8;     // 262144
    const int W_G   = (DM * DM) / 8;        // 32768
    int idx = blockIdx.x * 256 + threadIdx.x;
    if (idx >= CTX_G + 2 * W_G) return;

    const float* src;
    __nv_bfloat16* dst;
    if (idx < CTX_G) {
        src = ctx + (size_t)idx * 8;
        dst = g_Abf + (size_t)idx * 8;
    } else if (idx < CTX_G + W_G) {
        int j = idx - CTX_G;
        src = Wq + (size_t)j * 8;
        dst = g_Bbf + (size_t)j * 8;
    } else {
        int j = idx - CTX_G - W_G;
        src = Wk + (size_t)j * 8;
        dst = g_Bbf + (size_t)(W_G * 8) + (size_t)j * 8;
    }
    float4 v0 = *(const float4*)(src);
    float4 v1 = *(const float4*)(src + 4);
    __nv_bfloat162 b0 = __floats2bfloat162_rn(v0.x, v0.y);
    __nv_bfloat162 b1 = __floats2bfloat162_rn(v0.z, v0.w);
    __nv_bfloat162 b2 = __floats2bfloat162_rn(v1.x, v1.y);
    __nv_bfloat162 b3 = __floats2bfloat162_rn(v1.z, v1.w);
    uint4 packed;
    packed.x = *(unsigned*)&b0; packed.y = *(unsigned*)&b1;
    packed.z = *(unsigned*)&b2; packed.w = *(unsigned*)&b3;
    *(uint4*)dst = packed;
}

// -------------------- Kernel 1: fused GEMM + band epilogue + phrasal fill ------
// Block (h, m): C[64 tokens of tile m][ Qh 0..63 | Kh 64..127 ]; also streams
// its 65536-float slice of the constant phrasal tensor, overlapped with MMAs.
#define BN   128
#define BKK  64
#define KPAD 72
#define NSTAGE 3
#define STAGE_BYTES ((BM + BN) * KPAD * 2)       // 27648 per stage
#define AS_OFF      0
#define BS_OFF      (BM * KPAD * 2)              // 9216 within stage
#define CLD  132
#define SMEM_BIAS_OFF  (NSTAGE * STAGE_BYTES)    // 82944
#define SMEM_TOTAL_GEMM (SMEM_BIAS_OFF + 512)    // 83456
#define FILL_PER_BLOCK 65536                     // TOTAL / 512 blocks

__global__ __launch_bounds__(256) void gemm_band_kernel(
    const float* __restrict__ bq, const float* __restrict__ bk,
    float* __restrict__ outp, int write_ph)
{
    extern __shared__ char dsm[];
    float (*Cst)[CLD] = (float(*)[CLD])dsm;                 // reuses stages after MMAs
    float* bqs = (float*)(dsm + SMEM_BIAS_OFF);
    float* bks = bqs + DQ;

    const int h  = blockIdx.x;           // head 0..7
    const int m  = blockIdx.y;           // token tile 0..63
    const int tid  = threadIdx.x;        // 0..255
    const int warp = tid >> 5;           // 0..7
    const int lane = tid & 31;
    const int wm = warp & 1;             // 2 warps along M (32 rows)
    const int wn = warp >> 1;            // 4 warps along N (32 cols)

    // head-sliced biases into smem
    if (tid < DQ)             bqs[tid] = bq[h*DQ + tid];
    else if (tid < 2*DQ)      bks[tid - DQ] = bk[h*DQ + (tid - DQ)];

    wmma::fragment<wmma::accumulator,16,16,16,float> acc[2][2];
    #pragma unroll
    for (int mm = 0; mm < 2; mm++)
        #pragma unroll
        for (int nn = 0; nn < 2; nn++)
            wmma::fill_fragment(acc[mm][nn], 0.0f);

    // load mapping (BKK=64): A 64x64 bf16 = 512 uint4-chunks (2/thr);
    //                        B 128x64     = 1024 chunks (4/thr)
    int rA[2], cA[2];
    #pragma unroll
    for (int j = 0; j < 2; j++) {
        int idx = tid + 256*j;
        rA[j] = idx >> 3; cA[j] = (idx & 7) * 8;
    }
    int rB[4], cB[4];
    const __nv_bfloat16* srcB[4];
    #pragma unroll
    for (int j = 0; j < 4; j++) {
        int idx = tid + 256*j;
        rB[j] = idx >> 3; cB[j] = (idx & 7) * 8;
        int r = rB[j];
        int wrow = (r < DQ) ? (h*DQ + r) : (DM + h*DQ + (r - DQ));
        srcB[j] = &g_Bbf[(size_t)wrow * DM];
    }
    const __nv_bfloat16* srcA = &g_Abf[(size_t)(m*BM) * DM];

    unsigned dsmS = (unsigned)__cvta_generic_to_shared(dsm);
    unsigned dstA[2], dstB[4];
    #pragma unroll
    for (int j = 0; j < 2; j++) dstA[j] = dsmS + AS_OFF + (rA[j]*KPAD + cA[j]) * 2;
    #pragma unroll
    for (int j = 0; j < 4; j++) dstB[j] = dsmS + BS_OFF + (rB[j]*KPAD + cB[j]) * 2;

    #define LOAD_CHUNK(c) do { \
        const int _kg = (c) * BKK; \
        const unsigned _so = ((c) % NSTAGE) * STAGE_BYTES; \
        _Pragma("unroll") \
        for (int j = 0; j < 2; j++) \
            CP_ASYNC16(dstA[j] + _so, srcA + (size_t)rA[j]*DM + _kg + cA[j]); \
        _Pragma("unroll") \
        for (int j = 0; j < 4; j++) \
            CP_ASYNC16(dstB[j] + _so, srcB[j] + _kg + cB[j]); \
    } while(0)

    const int NIT = DM / BKK;  // 8

    // phrasal constant fill setup: this block's contiguous 65536-float slice
    const float SQRT_EPS = 3.1622776601683795e-5f;
    const float4 cfill = make_float4(SQRT_EPS, SQRT_EPS, SQRT_EPS, SQRT_EPS);
    float* fillp = outp + TOTAL + (size_t)(h * NTILE + m) * FILL_PER_BLOCK + tid * 4;

    // prologue: chunks 0,1
    LOAD_CHUNK(0); CP_COMMIT();
    LOAD_CHUNK(1); CP_COMMIT();

    for (int kt = 0; kt < NIT; kt++) {
        CP_WAIT1();                 // chunk kt landed (1 newer group may be pending)
        __syncthreads();            // all warps done reading slot (kt+2)%3

        if (kt + 2 < NIT) LOAD_CHUNK(kt + 2);
        CP_COMMIT();                // uniform group count (empty ok)

        const char* stg = dsm + (kt % NSTAGE) * STAGE_BYTES;
        const __nv_bfloat16 (*As)[KPAD] = (const __nv_bfloat16(*)[KPAD])(stg + AS_OFF);
        const __nv_bfloat16 (*Bs)[KPAD] = (const __nv_bfloat16(*)[KPAD])(stg + BS_OFF);

        #pragma unroll
        for (int kk = 0; kk < BKK; kk += 16) {
            wmma::fragment<wmma::matrix_a,16,16,16,__nv_bfloat16,wmma::row_major> af[2];
            wmma::fragment<wmma::matrix_b,16,16,16,__nv_bfloat16,wmma::col_major> bf[2];
            #pragma unroll
            for (int mm = 0; mm < 2; mm++)
                wmma::load_matrix_sync(af[mm], &As[wm*32 + mm*16][kk], KPAD);
            #pragma unroll
            for (int nn = 0; nn < 2; nn++)
                wmma::load_matrix_sync(bf[nn], &Bs[wn*32 + nn*16][kk], KPAD);
            #pragma unroll
            for (int mm = 0; mm < 2; mm++)
                #pragma unroll
                for (int nn = 0; nn < 2; nn++)
                    wmma::mma_sync(acc[mm][nn], af[mm], bf[nn], acc[mm][nn]);
        }

        // interleaved phrasal fill: 8 float4-rounds per iteration (64 total)
        if (write_ph) {
            float* fp = fillp + (size_t)kt * (8 * 1024);
            #pragma unroll
            for (int q = 0; q < 8; q++)
                __stcs((float4*)(fp + q * 1024), cfill);
        }
    }
    CP_WAIT0();
    __syncthreads();   // all warps done with stages before Cst overwrite

    // ---- stage C into smem ----
    #pragma unroll
    for (int mm = 0; mm < 2; mm++)
        #pragma unroll
        for (int nn = 0; nn < 2; nn++)
            wmma::store_matrix_sync(&Cst[wm*32 + mm*16][wn*32 + nn*16],
                                    acc[mm][nn], CLD, wmma::mem_row_major);
    __syncthreads();

    // ---- halo: biased q/k vectors at tile edges (rows 0 and 63) ----
    {
        int hm = (h*NTILE + m)*DQ;
        if (tid < DQ) {
            int d = tid;
            g_qF[hm + d] = Cst[0][d]      + bqs[d];
            g_kF[hm + d] = Cst[0][DQ + d] + bks[d];
        } else if (tid < 2*DQ) {
            int d = tid - DQ;
            g_qL[hm + d] = Cst[BM-1][d]      + bqs[d];
            g_kL[hm + d] = Cst[BM-1][DQ + d] + bks[d];
        }
    }

    // ---- interior banded dots: warp w -> rows w*8 .. w*8+7 ----
    const int d = lane * 2;
    float2 bqv = *(float2*)&bqs[d];
    float2 bkv = *(float2*)&bks[d];
    #pragma unroll
    for (int rr = 0; rr < 8; rr++) {
        int r = warp*8 + rr;
        float2 qv = *(float2*)&Cst[r][d];
        float q0 = qv.x + bqv.x, q1 = qv.y + bqv.y;
        float sf = 0.f, sb = 0.f;
        if (r < BM-1) {
            float2 kv = *(float2*)&Cst[r+1][DQ + d];
            sf = q0*(kv.x + bkv.x) + q1*(kv.y + bkv.y);
        }
        if (r > 0) {
            float2 kv = *(float2*)&Cst[r-1][DQ + d];
            sb = q0*(kv.x + bkv.x) + q1*(kv.y + bkv.y);
        }
        #pragma unroll
        for (int off = 16; off; off >>= 1) {
            sf += __shfl_down_sync(0xffffffffu, sf, off);
            sb += __shfl_down_sync(0xffffffffu, sb, off);
        }
        if (lane == 0) {
            int row = m*BM + r;
            int b = row >> 10;
            int i = row & (SEQ - 1);
            int idx = (b*NH + h)*SEQ + i;
            if (r < BM-1) g_Sf[idx] = sf * (1.0f / DM);
            if (r > 0)    g_Sb[idx] = sb * (1.0f / DM);
        }
    }
}

// -------------------- Kernel 2: boundary dots + softmax + prefix scan ----------
__global__ __launch_bounds__(1024) void scan_kernel(const int* __restrict__ amask)
{
    int bh = blockIdx.x;                 // 0..31
    int b  = bh >> 3;
    int h  = bh & 7;
    int t  = threadIdx.x;                // 0..1023
    int lane = t & 31, wid = t >> 5;

    __shared__ float b_sh[SEQ];
    __shared__ float wsum[32];
    __shared__ float sf_fix[TPB], sb_fix[TPB];

    // tile-boundary dots: warps 0..14 fwd (j=wid), warps 16..30 bwd (j=wid-15)
    if (wid < TPB-1) {
        int mm = b*TPB + wid;            // fwd at token t=64*wid+63
        float acc = 0.f;
        #pragma unroll
        for (int d = lane; d < DQ; d += 32)
            acc += g_qL[(h*NTILE + mm)*DQ + d] * g_kF[(h*NTILE + mm + 1)*DQ + d];
        #pragma unroll
        for (int off = 16; off; off >>= 1) acc += __shfl_down_sync(0xffffffffu, acc, off);
        if (lane == 0) sf_fix[wid] = acc * (1.0f / DM);
    } else if (wid >= 16 && wid < 16 + TPB-1) {
        int j = wid - 15;                // bwd at token t=64*j
        int mm = b*TPB + j;
        float acc = 0.f;
        #pragma unroll
        for (int d = lane; d < DQ; d += 32)
            acc += g_qF[(h*NTILE + mm)*DQ + d] * g_kL[(h*NTILE + mm - 1)*DQ + d];
        #pragma unroll
        for (int off = 16; off; off >>= 1) acc += __shfl_down_sync(0xffffffffu, acc, off);
        if (lane == 0) sb_fix[j] = acc * (1.0f / DM);
    }
    __syncthreads();

    float sf = g_Sf[bh*SEQ + t];
    float sb = g_Sb[bh*SEQ + t];
    if ((t & 63) == 63 && t < SEQ-1) sf = sf_fix[t >> 6];
    if ((t & 63) == 0  && t > 0)     sb = sb_fix[t >> 6];

    bool vf = (t < SEQ-1) && (amask[b*SEQ + t + 1] != 0);
    bool vb = (t > 0)     && (amask[b*SEQ + t - 1] != 0);

    float a, bb;
    if (vf | vb) {
        float mx = fmaxf(vf ? sf : -3.4e38f, vb ? sb : -3.4e38f);
        float ea = vf ? __expf(sf - mx) : 0.f;
        float eb = vb ? __expf(sb - mx) : 0.f;
        float den = ea + eb;
        a  = ea / den;
        bb = eb / den;
    } else {
        a = bb = 1.0f / SEQ;
    }
    b_sh[t] = bb;
    __syncthreads();

    float g = 0.f;
    if (t < SEQ-1) {
        float ph = sqrtf(a * b_sh[t+1] + 1e-9f);
        g_band[bh*SEQ + t] = ph;
        g = logf(ph + 1e-9f);
    }

    float incl = g;
    #pragma unroll
    for (int off = 1; off < 32; off <<= 1) {
        float n = __shfl_up_sync(0xffffffffu, incl, off);
        if (lane >= off) incl += n;
    }
    if (lane == 31) wsum[wid] = incl;
    __syncthreads();
    if (wid == 0) {
        float w = wsum[lane];
        #pragma unroll
        for (int off = 1; off < 32; off <<= 1) {
            float n = __shfl_up_sync(0xffffffffu, w, off);
            if (lane >= off) w += n;
        }
        wsum[lane] = w;
    }
    __syncthreads();
    float base = (wid > 0) ? wsum[wid-1] : 0.f;
    g_G[bh*SEQ + t] = base + incl - g;   // exclusive prefix
}

// -------------------- Kernel 3: attn rows + phrasal band patch -----------------
// G monotone decreasing (all g<0) => attn[i,k] = exp(-|G_k - G_i|) + eps, k != i.
// Phrasal constant already written by gemm fill; only band-containing float4s here.
__global__ __launch_bounds__(256) void out_kernel(float* __restrict__ out, int write_ph)
{
    const float SQRT_EPS = 3.1622776601683795e-5f;
    const float EPS = 1e-9f;

    int blk = blockIdx.x;                // bh*64 + rowTile
    int bh  = blk >> 6;
    int r0  = (blk & 63) << 4;           // first row i of 16
    int k0  = threadIdx.x << 2;

    const float* Gp = g_G + bh*SEQ;

    __shared__ float Gi_s[16];
    __shared__ float band_s[17];         // band[r0-1 .. r0+15]
    if (threadIdx.x < 16) Gi_s[threadIdx.x] = Gp[r0 + threadIdx.x];
    if (threadIdx.x < 17) {
        int ib = r0 - 1 + threadIdx.x;
        band_s[threadIdx.x] = (ib >= 0 && ib < SEQ-1) ? g_band[bh*SEQ + ib] : 0.f;
    }
    __syncthreads();

    float4 gk = *(const float4*)&Gp[k0];
    float* ptr  = out + (size_t)(bh*SEQ + r0) * SEQ + k0;
    float* pptr = ptr + TOTAL;

    const bool diag_col = ((unsigned)(r0 + 16) > (unsigned)k0) && (k0 + 4 > r0);
    // band patch can only occur for threads near the diagonal of this row tile
    const bool band_col = ((unsigned)(r0 + 17) > (unsigned)k0) && (k0 + 5 > r0);

    #pragma unroll
    for (int r = 0; r < 16; r++) {
        int i = r0 + r;
        float Gi = Gi_s[r];
        float4 o;
        o.x = __expf(-fabsf(gk.x - Gi)) + EPS;
        o.y = __expf(-fabsf(gk.y - Gi)) + EPS;
        o.z = __expf(-fabsf(gk.z - Gi)) + EPS;
        o.w = __expf(-fabsf(gk.w - Gi)) + EPS;
        if (diag_col) {
            int d = i - k0;
            if (d == 0) o.x = SQRT_EPS; else if (d == 1) o.y = SQRT_EPS;
            else if (d == 2) o.z = SQRT_EPS; else if (d == 3) o.w = SQRT_EPS;
        }
        __stcs((float4*)ptr, o);
        ptr += SEQ;

        if (write_ph && band_col) {
            int d1 = (i - 1) - k0;
            int d2 = (i + 1) - k0;
            if ((unsigned)d1 < 4u || (unsigned)d2 < 4u) {
                float4 p = make_float4(SQRT_EPS, SQRT_EPS, SQRT_EPS, SQRT_EPS);
                if ((unsigned)d1 < 4u) {
                    float v = band_s[r];
                    if (d1 == 0) p.x = v; else if (d1 == 1) p.y = v; else if (d1 == 2) p.z = v; else p.w = v;
                }
                if ((unsigned)d2 < 4u) {
                    float v = band_s[r + 1];
                    if (d2 == 0) p.x = v; else if (d2 == 1) p.y = v; else if (d2 == 2) p.z = v; else p.w = v;
                }
                __stcs((float4*)pptr, p);
            }
        }
        pptr += SEQ;
    }
}

// -------------------- launch ---------------------------------------------------
extern "C" void kernel_launch(void* const* d_in, const int* in_sizes, int n_in,
                              void* d_out, int out_size)
{
    const float* ctx   = (const float*)d_in[0];   // (4,1024,512) fp32
    const int*   amask = (const int*)  d_in[1];   // (4,1024) int32
    const float* Wq    = (const float*)d_in[2];   // (512,512)
    const float* bq    = (const float*)d_in[3];   // (512,)
    const float* Wk    = (const float*)d_in[4];   // (512,512)
    const float* bk    = (const float*)d_in[5];   // (512,)
    float* out = (float*)d_out;

    int write_ph = ((long long)out_size >= 2 * (long long)TOTAL) ? 1 : 0;

    cudaFuncSetAttribute(gemm_band_kernel,
                         cudaFuncAttributeMaxDynamicSharedMemorySize, SMEM_TOTAL_GEMM);

    const int CVT_G = (M_TOT*DM + 2*DM*DM) / 8;   // 327680 groups
    cvt_kernel<<<(CVT_G + 255) / 256, 256>>>(ctx, Wq, Wk);

    dim3 ggrid(NH, NTILE);               // (8, 64)
    gemm_band_kernel<<<ggrid, 256, SMEM_TOTAL_GEMM>>>(bq, bk, out, write_ph);
    scan_kernel<<<NBH, 1024>>>(amask);
    out_kernel<<<NBH * SEQ / 16, 256>>>(out, write_ph);
}

// round 17
// speedup vs baseline: 1.1981x; 1.0125x over previous
#include <cuda_runtime.h>
#include <cuda_bf16.h>
#include <mma.h>
#include <math.h>

using namespace nvcuda;

// Problem constants (fixed shapes)
#define BSZ   4
#define SEQ   1024
#define DM    512
#define NH    8
#define DQ    64
#define M_TOT (BSZ*SEQ)     // 4096 tokens
#define NBH   (BSZ*NH)      // 32 (batch,head) pairs
#define BM    64            // token tile rows
#define NTILE (M_TOT/BM)    // 64 token tiles
#define TPB   16            // tiles per batch
#define TOTAL ((size_t)NBH * SEQ * SEQ)   // 33,554,432 elements per tensor

// -------------------- device scratch --------------------
__device__ __nv_bfloat16 g_Abf[M_TOT * DM];   // 4 MB bf16 ctx
__device__ __nv_bfloat16 g_Bbf[2*DM * DM];    // 1 MB bf16 [Wq;Wk]
__device__ float g_Sf[NBH * SEQ];
__device__ float g_Sb[NBH * SEQ];
__device__ float g_G [NBH * SEQ];
__device__ float g_band[NBH * SEQ];
// halo: biased q/k vectors at tile edges, [head][tile][64]
__device__ float g_qF[NH * NTILE * DQ];
__device__ float g_qL[NH * NTILE * DQ];
__device__ float g_kF[NH * NTILE * DQ];
__device__ float g_kL[NH * NTILE * DQ];

// -------------------- cp.async / barrier helpers --------------------
#define CP_ASYNC16(dst_u32, src_ptr) \
    asm volatile("cp.async.cg.shared.global [%0], [%1], 16;\n" :: "r"(dst_u32), "l"(src_ptr))
#define CP_COMMIT() asm volatile("cp.async.commit_group;\n" ::: "memory")
#define CP_WAIT1()  asm volatile("cp.async.wait_group 1;\n" ::: "memory")
#define CP_WAIT0()  asm volatile("cp.async.wait_group 0;\n" ::: "memory")
// barrier among the 256 MMA threads only (fill warps never arrive)
#define MMA_BAR()   asm volatile("bar.sync 1, 256;" ::: "memory")

// -------------------- Kernel 0: fp32 -> bf16 conversion prepass ----------------
__global__ __launch_bounds__(256) void cvt_kernel(
    const float* __restrict__ ctx,
    const float* __restrict__ Wq,
    const float* __restrict__ Wk)
{
    const int CTX_G = (M_TOT * DM) / 8;     // 262144
    const int W_G   = (DM * DM) / 8;        // 32768
    int idx = blockIdx.x * 256 + threadIdx.x;
    if (idx >= CTX_G + 2 * W_G) return;

    const float* src;
    __nv_bfloat16* dst;
    if (idx < CTX_G) {
        src = ctx + (size_t)idx * 8;
        dst = g_Abf + (size_t)idx * 8;
    } else if (idx < CTX_G + W_G) {
        int j = idx - CTX_G;
        src = Wq + (size_t)j * 8;
        dst = g_Bbf + (size_t)j * 8;
    } else {
        int j = idx - CTX_G - W_G;
        src = Wk + (size_t)j * 8;
        dst = g_Bbf + (size_t)(W_G * 8) + (size_t)j * 8;
    }
    float4 v0 = *(const float4*)(src);
    float4 v1 = *(const float4*)(src + 4);
    __nv_bfloat162 b0 = __floats2bfloat162_rn(v0.x, v0.y);
    __nv_bfloat162 b1 = __floats2bfloat162_rn(v0.z, v0.w);
    __nv_bfloat162 b2 = __floats2bfloat162_rn(v1.x, v1.y);
    __nv_bfloat162 b3 = __floats2bfloat162_rn(v1.z, v1.w);
    uint4 packed;
    packed.x = *(unsigned*)&b0; packed.y = *(unsigned*)&b1;
    packed.z = *(unsigned*)&b2; packed.w = *(unsigned*)&b3;
    *(uint4*)dst = packed;
}

// -------------------- Kernel 1: GEMM (warps 0-7) + phrasal fill (warps 8-9) ----
// Block (h, m): C[64 tokens of tile m][ Qh 0..63 | Kh 64..127 ]. Fill warps
// stream the block's 65536-float constant phrasal slice from cycle 0.
#define BN   128
#define BKK  64
#define KPAD 72
#define NSTAGE 3
#define STAGE_BYTES ((BM + BN) * KPAD * 2)       // 27648 per stage
#define AS_OFF      0
#define BS_OFF      (BM * KPAD * 2)              // 9216 within stage
#define CLD  132
#define SMEM_BIAS_OFF  (NSTAGE * STAGE_BYTES)    // 82944
#define SMEM_TOTAL_GEMM (SMEM_BIAS_OFF + 512)    // 83456
#define FILL_PER_BLOCK 65536                     // TOTAL / 512 blocks
#define GEMM_THREADS 320

__global__ __launch_bounds__(GEMM_THREADS) void gemm_band_kernel(
    const float* __restrict__ bq, const float* __restrict__ bk,
    float* __restrict__ outp, int write_ph)
{
    extern __shared__ char dsm[];
    float (*Cst)[CLD] = (float(*)[CLD])dsm;                 // reuses stages after MMAs
    float* bqs = (float*)(dsm + SMEM_BIAS_OFF);
    float* bks = bqs + DQ;

    const int h  = blockIdx.x;           // head 0..7
    const int m  = blockIdx.y;           // token tile 0..63
    const int tid  = threadIdx.x;        // 0..319
    const int warp = tid >> 5;           // 0..9
    const int lane = tid & 31;

    // ================= fill warps (8,9): stream constant phrasal slice ========
    if (warp >= 8) {
        if (write_ph) {
            const float SQRT_EPS = 3.1622776601683795e-5f;
            const float4 cfill = make_float4(SQRT_EPS, SQRT_EPS, SQRT_EPS, SQRT_EPS);
            int ft = tid - 256;          // 0..63
            float* fp = outp + TOTAL + (size_t)(h * NTILE + m) * FILL_PER_BLOCK + ft * 4;
            #pragma unroll 4
            for (int q = 0; q < FILL_PER_BLOCK / (64 * 4); q++)   // 256 rounds of 1KB
                __stcs((float4*)(fp + (size_t)q * 256), cfill);
        }
        return;
    }

    // ================= MMA warps (0-7) ========================================
    const int wm = warp & 1;             // 2 warps along M (32 rows)
    const int wn = warp >> 1;            // 4 warps along N (32 cols)

    // head-sliced biases into smem
    if (tid < DQ)             bqs[tid] = bq[h*DQ + tid];
    else if (tid < 2*DQ)      bks[tid - DQ] = bk[h*DQ + (tid - DQ)];

    wmma::fragment<wmma::accumulator,16,16,16,float> acc[2][2];
    #pragma unroll
    for (int mm = 0; mm < 2; mm++)
        #pragma unroll
        for (int nn = 0; nn < 2; nn++)
            wmma::fill_fragment(acc[mm][nn], 0.0f);

    // load mapping (BKK=64): A 64x64 bf16 = 512 uint4-chunks (2/thr);
    //                        B 128x64     = 1024 chunks (4/thr)
    int rA[2], cA[2];
    #pragma unroll
    for (int j = 0; j < 2; j++) {
        int idx = tid + 256*j;
        rA[j] = idx >> 3; cA[j] = (idx & 7) * 8;
    }
    int rB[4], cB[4];
    const __nv_bfloat16* srcB[4];
    #pragma unroll
    for (int j = 0; j < 4; j++) {
        int idx = tid + 256*j;
        rB[j] = idx >> 3; cB[j] = (idx & 7) * 8;
        int r = rB[j];
        int wrow = (r < DQ) ? (h*DQ + r) : (DM + h*DQ + (r - DQ));
        srcB[j] = &g_Bbf[(size_t)wrow * DM];
    }
    const __nv_bfloat16* srcA = &g_Abf[(size_t)(m*BM) * DM];

    unsigned dsmS = (unsigned)__cvta_generic_to_shared(dsm);
    unsigned dstA[2], dstB[4];
    #pragma unroll
    for (int j = 0; j < 2; j++) dstA[j] = dsmS + AS_OFF + (rA[j]*KPAD + cA[j]) * 2;
    #pragma unroll
    for (int j = 0; j < 4; j++) dstB[j] = dsmS + BS_OFF + (rB[j]*KPAD + cB[j]) * 2;

    #define LOAD_CHUNK(c) do { \
        const int _kg = (c) * BKK; \
        const unsigned _so = ((c) % NSTAGE) * STAGE_BYTES; \
        _Pragma("unroll") \
        for (int j = 0; j < 2; j++) \
            CP_ASYNC16(dstA[j] + _so, srcA + (size_t)rA[j]*DM + _kg + cA[j]); \
        _Pragma("unroll") \
        for (int j = 0; j < 4; j++) \
            CP_ASYNC16(dstB[j] + _so, srcB[j] + _kg + cB[j]); \
    } while(0)

    const int NIT = DM / BKK;  // 8

    // prologue: chunks 0,1
    LOAD_CHUNK(0); CP_COMMIT();
    LOAD_CHUNK(1); CP_COMMIT();

    for (int kt = 0; kt < NIT; kt++) {
        CP_WAIT1();                 // chunk kt landed (1 newer group may be pending)
        MMA_BAR();                  // all MMA warps done reading slot (kt+2)%3

        if (kt + 2 < NIT) LOAD_CHUNK(kt + 2);
        CP_COMMIT();                // uniform group count (empty ok)

        const char* stg = dsm + (kt % NSTAGE) * STAGE_BYTES;
        const __nv_bfloat16 (*As)[KPAD] = (const __nv_bfloat16(*)[KPAD])(stg + AS_OFF);
        const __nv_bfloat16 (*Bs)[KPAD] = (const __nv_bfloat16(*)[KPAD])(stg + BS_OFF);

        #pragma unroll
        for (int kk = 0; kk < BKK; kk += 16) {
            wmma::fragment<wmma::matrix_a,16,16,16,__nv_bfloat16,wmma::row_major> af[2];
            wmma::fragment<wmma::matrix_b,16,16,16,__nv_bfloat16,wmma::col_major> bf[2];
            #pragma unroll
            for (int mm = 0; mm < 2; mm++)
                wmma::load_matrix_sync(af[mm], &As[wm*32 + mm*16][kk], KPAD);
            #pragma unroll
            for (int nn = 0; nn < 2; nn++)
                wmma::load_matrix_sync(bf[nn], &Bs[wn*32 + nn*16][kk], KPAD);
            #pragma unroll
            for (int mm = 0; mm < 2; mm++)
                #pragma unroll
                for (int nn = 0; nn < 2; nn++)
                    wmma::mma_sync(acc[mm][nn], af[mm], bf[nn], acc[mm][nn]);
        }
    }
    CP_WAIT0();
    MMA_BAR();   // all MMA warps done with stages before Cst overwrite

    // ---- stage C into smem ----
    #pragma unroll
    for (int mm = 0; mm < 2; mm++)
        #pragma unroll
        for (int nn = 0; nn < 2; nn++)
            wmma::store_matrix_sync(&Cst[wm*32 + mm*16][wn*32 + nn*16],
                                    acc[mm][nn], CLD, wmma::mem_row_major);
    MMA_BAR();

    // ---- halo: biased q/k vectors at tile edges (rows 0 and 63) ----
    {
        int hm = (h*NTILE + m)*DQ;
        if (tid < DQ) {
            int d = tid;
            g_qF[hm + d] = Cst[0][d]      + bqs[d];
            g_kF[hm + d] = Cst[0][DQ + d] + bks[d];
        } else if (tid < 2*DQ) {
            int d = tid - DQ;
            g_qL[hm + d] = Cst[BM-1][d]      + bqs[d];
            g_kL[hm + d] = Cst[BM-1][DQ + d] + bks[d];
        }
    }

    // ---- interior banded dots: warp w -> rows w*8 .. w*8+7 ----
    const int d = lane * 2;
    float2 bqv = *(float2*)&bqs[d];
    float2 bkv = *(float2*)&bks[d];
    #pragma unroll
    for (int rr = 0; rr < 8; rr++) {
        int r = warp*8 + rr;
        float2 qv = *(float2*)&Cst[r][d];
        float q0 = qv.x + bqv.x, q1 = qv.y + bqv.y;
        float sf = 0.f, sb = 0.f;
        if (r < BM-1) {
            float2 kv = *(float2*)&Cst[r+1][DQ + d];
            sf = q0*(kv.x + bkv.x) + q1*(kv.y + bkv.y);
        }
        if (r > 0) {
            float2 kv = *(float2*)&Cst[r-1][DQ + d];
            sb = q0*(kv.x + bkv.x) + q1*(kv.y + bkv.y);
        }
        #pragma unroll
        for (int off = 16; off; off >>= 1) {
            sf += __shfl_down_sync(0xffffffffu, sf, off);
            sb += __shfl_down_sync(0xffffffffu, sb, off);
        }
        if (lane == 0) {
            int row = m*BM + r;
            int b = row >> 10;
            int i = row & (SEQ - 1);
            int idx = (b*NH + h)*SEQ + i;
            if (r < BM-1) g_Sf[idx] = sf * (1.0f / DM);
            if (r > 0)    g_Sb[idx] = sb * (1.0f / DM);
        }
    }
}

// -------------------- Kernel 2: boundary dots + softmax + prefix scan ----------
__global__ __launch_bounds__(1024) void scan_kernel(const int* __restrict__ amask)
{
    int bh = blockIdx.x;                 // 0..31
    int b  = bh >> 3;
    int h  = bh & 7;
    int t  = threadIdx.x;                // 0..1023
    int lane = t & 31, wid = t >> 5;

    __shared__ float b_sh[SEQ];
    __shared__ float wsum[32];
    __shared__ float sf_fix[TPB], sb_fix[TPB];

    // tile-boundary dots: warps 0..14 fwd (j=wid), warps 16..30 bwd (j=wid-15)
    if (wid < TPB-1) {
        int mm = b*TPB + wid;            // fwd at token t=64*wid+63
        float acc = 0.f;
        #pragma unroll
        for (int d = lane; d < DQ; d += 32)
            acc += g_qL[(h*NTILE + mm)*DQ + d] * g_kF[(h*NTILE + mm + 1)*DQ + d];
        #pragma unroll
        for (int off = 16; off; off >>= 1) acc += __shfl_down_sync(0xffffffffu, acc, off);
        if (lane == 0) sf_fix[wid] = acc * (1.0f / DM);
    } else if (wid >= 16 && wid < 16 + TPB-1) {
        int j = wid - 15;                // bwd at token t=64*j
        int mm = b*TPB + j;
        float acc = 0.f;
        #pragma unroll
        for (int d = lane; d < DQ; d += 32)
            acc += g_qF[(h*NTILE + mm)*DQ + d] * g_kL[(h*NTILE + mm - 1)*DQ + d];
        #pragma unroll
        for (int off = 16; off; off >>= 1) acc += __shfl_down_sync(0xffffffffu, acc, off);
        if (lane == 0) sb_fix[j] = acc * (1.0f / DM);
    }
    __syncthreads();

    float sf = g_Sf[bh*SEQ + t];
    float sb = g_Sb[bh*SEQ + t];
    if ((t & 63) == 63 && t < SEQ-1) sf = sf_fix[t >> 6];
    if ((t & 63) == 0  && t > 0)     sb = sb_fix[t >> 6];

    bool vf = (t < SEQ-1) && (amask[b*SEQ + t + 1] != 0);
    bool vb = (t > 0)     && (amask[b*SEQ + t - 1] != 0);

    float a, bb;
    if (vf | vb) {
        float mx = fmaxf(vf ? sf : -3.4e38f, vb ? sb : -3.4e38f);
        float ea = vf ? __expf(sf - mx) : 0.f;
        float eb = vb ? __expf(sb - mx) : 0.f;
        float den = ea + eb;
        a  = ea / den;
        bb = eb / den;
    } else {
        a = bb = 1.0f / SEQ;
    }
    b_sh[t] = bb;
    __syncthreads();

    float g = 0.f;
    if (t < SEQ-1) {
        float ph = sqrtf(a * b_sh[t+1] + 1e-9f);
        g_band[bh*SEQ + t] = ph;
        g = logf(ph + 1e-9f);
    }

    float incl = g;
    #pragma unroll
    for (int off = 1; off < 32; off <<= 1) {
        float n = __shfl_up_sync(0xffffffffu, incl, off);
        if (lane >= off) incl += n;
    }
    if (lane == 31) wsum[wid] = incl;
    __syncthreads();
    if (wid == 0) {
        float w = wsum[lane];
        #pragma unroll
        for (int off = 1; off < 32; off <<= 1) {
            float n = __shfl_up_sync(0xffffffffu, w, off);
            if (lane >= off) w += n;
        }
        wsum[lane] = w;
    }
    __syncthreads();
    float base = (wid > 0) ? wsum[wid-1] : 0.f;
    g_G[bh*SEQ + t] = base + incl - g;   // exclusive prefix
}

// -------------------- Kernel 3: attn rows + phrasal band patch -----------------
// G monotone decreasing (all g<0) => attn[i,k] = exp(-|G_k - G_i|) + eps, k != i.
// Phrasal constant already written by gemm fill; only band-containing float4s here.
__global__ __launch_bounds__(256) void out_kernel(float* __restrict__ out, int write_ph)
{
    const float SQRT_EPS = 3.1622776601683795e-5f;
    const float EPS = 1e-9f;

    int blk = blockIdx.x;                // bh*64 + rowTile
    int bh  = blk >> 6;
    int r0  = (blk & 63) << 4;           // first row i of 16
    int k0  = threadIdx.x << 2;

    const float* Gp = g_G + bh*SEQ;

    __shared__ float Gi_s[16];
    __shared__ float band_s[17];         // band[r0-1 .. r0+15]
    if (threadIdx.x < 16) Gi_s[threadIdx.x] = Gp[r0 + threadIdx.x];
    if (threadIdx.x < 17) {
        int ib = r0 - 1 + threadIdx.x;
        band_s[threadIdx.x] = (ib >= 0 && ib < SEQ-1) ? g_band[bh*SEQ + ib] : 0.f;
    }
    __syncthreads();

    float4 gk = *(const float4*)&Gp[k0];
    float* ptr  = out + (size_t)(bh*SEQ + r0) * SEQ + k0;
    float* pptr = ptr + TOTAL;

    const bool diag_col = ((unsigned)(r0 + 16) > (unsigned)k0) && (k0 + 4 > r0);
    const bool band_col = ((unsigned)(r0 + 17) > (unsigned)k0) && (k0 + 5 > r0);

    #pragma unroll
    for (int r = 0; r < 16; r++) {
        int i = r0 + r;
        float Gi = Gi_s[r];
        float4 o;
        o.x = __expf(-fabsf(gk.x - Gi)) + EPS;
        o.y = __expf(-fabsf(gk.y - Gi)) + EPS;
        o.z = __expf(-fabsf(gk.z - Gi)) + EPS;
        o.w = __expf(-fabsf(gk.w - Gi)) + EPS;
        if (diag_col) {
            int d = i - k0;
            if (d == 0) o.x = SQRT_EPS; else if (d == 1) o.y = SQRT_EPS;
            else if (d == 2) o.z = SQRT_EPS; else if (d == 3) o.w = SQRT_EPS;
        }
        __stcs((float4*)ptr, o);
        ptr += SEQ;

        if (write_ph && band_col) {
            int d1 = (i - 1) - k0;
            int d2 = (i + 1) - k0;
            if ((unsigned)d1 < 4u || (unsigned)d2 < 4u) {
                float4 p = make_float4(SQRT_EPS, SQRT_EPS, SQRT_EPS, SQRT_EPS);
                if ((unsigned)d1 < 4u) {
                    float v = band_s[r];
                    if (d1 == 0) p.x = v; else if (d1 == 1) p.y = v; else if (d1 == 2) p.z = v; else p.w = v;
                }
                if ((unsigned)d2 < 4u) {
                    float v = band_s[r + 1];
                    if (d2 == 0) p.x = v; else if (d2 == 1) p.y = v; else if (d2 == 2) p.z = v; else p.w = v;
                }
                __stcs((float4*)pptr, p);
            }
        }
        pptr += SEQ;
    }
}

// -------------------- launch ---------------------------------------------------
extern "C" void kernel_launch(void* const* d_in, const int* in_sizes, int n_in,
                              void* d_out, int out_size)
{
    const float* ctx   = (const float*)d_in[0];   // (4,1024,512) fp32
    const int*   amask = (const int*)  d_in[1];   // (4,1024) int32
    const float* Wq    = (const float*)d_in[2];   // (512,512)
    const float* bq    = (const float*)d_in[3];   // (512,)
    const float* Wk    = (const float*)d_in[4];   // (512,512)
    const float* bk    = (const float*)d_in[5];   // (512,)
    float* out = (float*)d_out;

    int write_ph = ((long long)out_size >= 2 * (long long)TOTAL) ? 1 : 0;

    cudaFuncSetAttribute(gemm_band_kernel,
                         cudaFuncAttributeMaxDynamicSharedMemorySize, SMEM_TOTAL_GEMM);

    const int CVT_G = (M_TOT*DM + 2*DM*DM) / 8;   // 327680 groups
    cvt_kernel<<<(CVT_G + 255) / 256, 256>>>(ctx, Wq, Wk);

    dim3 ggrid(NH, NTILE);               // (8, 64)
    gemm_band_kernel<<<ggrid, GEMM_THREADS, SMEM_TOTAL_GEMM>>>(bq, bk, out, write_ph);
    scan_kernel<<<NBH, 1024>>>(amask);
    out_kernel<<<NBH * SEQ / 16, 256>>>(out, write_ph);
}